// round 2
// baseline (speedup 1.0000x reference)
#include <cuda_runtime.h>
#include <cuda_bf16.h>
#include <math.h>

#define NPATCH 8192
#define KC     10
#define DIN    1024
#define DH     512
#define DA     256
#define NCLS   4
#define BK     16

// ---------------- device scratch (no allocations allowed) ----------------
__device__ int   g_cnt[KC];
__device__ int   g_off[KC + 1];
__device__ int   g_cursor[KC];
__device__ int   g_order[NPATCH];
__device__ float g_H1[(size_t)NPATCH * DH];     // 16 MB
__device__ float g_psum[KC * DH];

typedef unsigned long long u64;

#define FMA2(d, a, b) asm("fma.rn.f32x2 %0, %1, %2, %0;" : "+l"(d) : "l"(a), "l"(b))

__device__ __forceinline__ float2 u2f(u64 v) {
    float2 f;
    asm("mov.b64 {%0,%1}, %2;" : "=f"(f.x), "=f"(f.y) : "l"(v));
    return f;
}

// ---------------- small setup kernels ----------------
__global__ void k_init() {
    int tid = blockIdx.x * blockDim.x + threadIdx.x;
    if (tid < KC) { g_cnt[tid] = 0; g_cursor[tid] = 0; }
    for (int i = tid; i < KC * DH; i += gridDim.x * blockDim.x) g_psum[i] = 0.f;
}

__global__ void k_hist(const int* __restrict__ cid, int n) {
    int i = blockIdx.x * blockDim.x + threadIdx.x;
    if (i < n) atomicAdd(&g_cnt[cid[i]], 1);
}

__global__ void k_offsets() {
    int s = 0;
    g_off[0] = 0;
    for (int k = 0; k < KC; k++) { s += g_cnt[k]; g_off[k + 1] = s; }
}

__global__ void k_scatter(const int* __restrict__ cid, int n) {
    int i = blockIdx.x * blockDim.x + threadIdx.x;
    if (i < n) {
        int c = cid[i];
        int pos = g_off[c] + atomicAdd(&g_cursor[c], 1);
        g_order[pos] = i;
    }
}

// ============ shared GEMM machinery: 128x128 tile, BK=16, f32x2 FFMA2 ============
// acc[p][j] packs rows (ty*8+2p, ty*8+2p+1), col tx*8+j

// ---------------- GEMM1: H1[r,:] = relu(x[order[r],:] @ W1[k] + b1[k]) ----------------
__global__ __launch_bounds__(256, 2) void k_gemm1(const float* __restrict__ x,
                                                  const float* __restrict__ W1,
                                                  const float* __restrict__ b1) {
    int k = blockIdx.z;
    int rend = g_off[k + 1];
    int row0 = g_off[k] + blockIdx.y * 128;
    if (row0 >= rend) return;
    int col0 = blockIdx.x * 128;

    __shared__ __align__(16) float As[BK * 128];   // As[kk][row], 8KB
    __shared__ __align__(16) float Bs[BK * 256];   // duplicated pairs Bs[kk][col*2+{0,1}], 16KB

    int tid = threadIdx.x;
    int tx = tid & 15, ty = tid >> 4;

    u64 acc[4][8];
#pragma unroll
    for (int p = 0; p < 4; p++)
#pragma unroll
        for (int j = 0; j < 8; j++) acc[p][j] = 0ull;

    // A loader: 2 threads per row, 8 k each
    int arow = tid >> 1;
    int ak = (tid & 1) * 8;
    int grow = row0 + arow;
    bool rvalid = grow < rend;
    const float* aptr = x + (rvalid ? (size_t)g_order[grow] * DIN : 0) + ak;

    // B loader: 16 threads per k-row, 8 cols each
    int bkr = tid >> 4;
    int bcol = (tid & 15) * 8;
    const float* bptr = W1 + (size_t)k * DIN * DH + (size_t)bkr * DH + col0 + bcol;

    float4 pa0, pa1, pb0, pb1;
    pa0 = rvalid ? *(const float4*)(aptr)     : make_float4(0, 0, 0, 0);
    pa1 = rvalid ? *(const float4*)(aptr + 4) : make_float4(0, 0, 0, 0);
    pb0 = *(const float4*)(bptr);
    pb1 = *(const float4*)(bptr + 4);

    const int nsteps = DIN / BK;
    for (int s = 0; s < nsteps; s++) {
        // store staged tile
        As[(ak + 0) * 128 + arow] = pa0.x; As[(ak + 1) * 128 + arow] = pa0.y;
        As[(ak + 2) * 128 + arow] = pa0.z; As[(ak + 3) * 128 + arow] = pa0.w;
        As[(ak + 4) * 128 + arow] = pa1.x; As[(ak + 5) * 128 + arow] = pa1.y;
        As[(ak + 6) * 128 + arow] = pa1.z; As[(ak + 7) * 128 + arow] = pa1.w;
        {
            float v[8] = {pb0.x, pb0.y, pb0.z, pb0.w, pb1.x, pb1.y, pb1.z, pb1.w};
#pragma unroll
            for (int i = 0; i < 8; i++)
                *(float2*)&Bs[bkr * 256 + (bcol + i) * 2] = make_float2(v[i], v[i]);
        }
        __syncthreads();

        // prefetch next tile
        if (s + 1 < nsteps) {
            aptr += BK;
            bptr += (size_t)BK * DH;
            pa0 = rvalid ? *(const float4*)(aptr)     : make_float4(0, 0, 0, 0);
            pa1 = rvalid ? *(const float4*)(aptr + 4) : make_float4(0, 0, 0, 0);
            pb0 = *(const float4*)(bptr);
            pb1 = *(const float4*)(bptr + 4);
        }

#pragma unroll
        for (int kk = 0; kk < BK; kk++) {
            ulonglong2 av0 = *(const ulonglong2*)&As[kk * 128 + ty * 8];
            ulonglong2 av1 = *(const ulonglong2*)&As[kk * 128 + ty * 8 + 4];
            u64 a2[4] = {av0.x, av0.y, av1.x, av1.y};
            ulonglong2 bv0 = *(const ulonglong2*)&Bs[kk * 256 + tx * 16];
            ulonglong2 bv1 = *(const ulonglong2*)&Bs[kk * 256 + tx * 16 + 4];
            ulonglong2 bv2 = *(const ulonglong2*)&Bs[kk * 256 + tx * 16 + 8];
            ulonglong2 bv3 = *(const ulonglong2*)&Bs[kk * 256 + tx * 16 + 12];
            u64 b2[8] = {bv0.x, bv0.y, bv1.x, bv1.y, bv2.x, bv2.y, bv3.x, bv3.y};
#pragma unroll
            for (int p = 0; p < 4; p++)
#pragma unroll
                for (int j = 0; j < 8; j++) FMA2(acc[p][j], a2[p], b2[j]);
        }
        __syncthreads();
    }

    // epilogue: bias + relu + store
    const float* bias = b1 + k * DH + col0 + tx * 8;
    float bv[8];
#pragma unroll
    for (int j = 0; j < 8; j++) bv[j] = bias[j];
#pragma unroll
    for (int p = 0; p < 4; p++) {
        int r = row0 + ty * 8 + 2 * p;
        float* d0 = g_H1 + (size_t)r * DH + col0 + tx * 8;
        if (r < rend) {
#pragma unroll
            for (int j = 0; j < 8; j++) {
                float2 v = u2f(acc[p][j]);
                d0[j] = fmaxf(v.x + bv[j], 0.f);
            }
        }
        if (r + 1 < rend) {
#pragma unroll
            for (int j = 0; j < 8; j++) {
                float2 v = u2f(acc[p][j]);
                d0[DH + j] = fmaxf(v.y + bv[j], 0.f);
            }
        }
    }
}

// ---------------- GEMM2: psum[k,:] += colsum( relu(H1 @ W2[k] + b2[k]) ) ----------------
__global__ __launch_bounds__(256, 2) void k_gemm2(const float* __restrict__ W2,
                                                  const float* __restrict__ b2) {
    int k = blockIdx.z;
    int rend = g_off[k + 1];
    int row0 = g_off[k] + blockIdx.y * 128;
    if (row0 >= rend) return;
    int col0 = blockIdx.x * 128;

    __shared__ __align__(16) float As[BK * 128];
    __shared__ __align__(16) float Bs[BK * 256];

    int tid = threadIdx.x;
    int tx = tid & 15, ty = tid >> 4;

    u64 acc[4][8];
#pragma unroll
    for (int p = 0; p < 4; p++)
#pragma unroll
        for (int j = 0; j < 8; j++) acc[p][j] = 0ull;

    int arow = tid >> 1;
    int ak = (tid & 1) * 8;
    int grow = row0 + arow;
    bool rvalid = grow < rend;
    const float* aptr = g_H1 + (rvalid ? (size_t)grow * DH : 0) + ak;

    int bkr = tid >> 4;
    int bcol = (tid & 15) * 8;
    const float* bptr = W2 + (size_t)k * DH * DH + (size_t)bkr * DH + col0 + bcol;

    float4 pa0, pa1, pb0, pb1;
    pa0 = rvalid ? *(const float4*)(aptr)     : make_float4(0, 0, 0, 0);
    pa1 = rvalid ? *(const float4*)(aptr + 4) : make_float4(0, 0, 0, 0);
    pb0 = *(const float4*)(bptr);
    pb1 = *(const float4*)(bptr + 4);

    const int nsteps = DH / BK;
    for (int s = 0; s < nsteps; s++) {
        As[(ak + 0) * 128 + arow] = pa0.x; As[(ak + 1) * 128 + arow] = pa0.y;
        As[(ak + 2) * 128 + arow] = pa0.z; As[(ak + 3) * 128 + arow] = pa0.w;
        As[(ak + 4) * 128 + arow] = pa1.x; As[(ak + 5) * 128 + arow] = pa1.y;
        As[(ak + 6) * 128 + arow] = pa1.z; As[(ak + 7) * 128 + arow] = pa1.w;
        {
            float v[8] = {pb0.x, pb0.y, pb0.z, pb0.w, pb1.x, pb1.y, pb1.z, pb1.w};
#pragma unroll
            for (int i = 0; i < 8; i++)
                *(float2*)&Bs[bkr * 256 + (bcol + i) * 2] = make_float2(v[i], v[i]);
        }
        __syncthreads();

        if (s + 1 < nsteps) {
            aptr += BK;
            bptr += (size_t)BK * DH;
            pa0 = rvalid ? *(const float4*)(aptr)     : make_float4(0, 0, 0, 0);
            pa1 = rvalid ? *(const float4*)(aptr + 4) : make_float4(0, 0, 0, 0);
            pb0 = *(const float4*)(bptr);
            pb1 = *(const float4*)(bptr + 4);
        }

#pragma unroll
        for (int kk = 0; kk < BK; kk++) {
            ulonglong2 av0 = *(const ulonglong2*)&As[kk * 128 + ty * 8];
            ulonglong2 av1 = *(const ulonglong2*)&As[kk * 128 + ty * 8 + 4];
            u64 a2[4] = {av0.x, av0.y, av1.x, av1.y};
            ulonglong2 bv0 = *(const ulonglong2*)&Bs[kk * 256 + tx * 16];
            ulonglong2 bv1 = *(const ulonglong2*)&Bs[kk * 256 + tx * 16 + 4];
            ulonglong2 bv2 = *(const ulonglong2*)&Bs[kk * 256 + tx * 16 + 8];
            ulonglong2 bv3 = *(const ulonglong2*)&Bs[kk * 256 + tx * 16 + 12];
            u64 b2v[8] = {bv0.x, bv0.y, bv1.x, bv1.y, bv2.x, bv2.y, bv3.x, bv3.y};
#pragma unroll
            for (int p = 0; p < 4; p++)
#pragma unroll
                for (int j = 0; j < 8; j++) FMA2(acc[p][j], a2[p], b2v[j]);
        }
        __syncthreads();
    }

    // epilogue: bias + relu + column sums over valid rows
    const float* bias = b2 + k * DH + col0 + tx * 8;
    float bv[8];
#pragma unroll
    for (int j = 0; j < 8; j++) bv[j] = bias[j];
    float csum[8];
#pragma unroll
    for (int j = 0; j < 8; j++) csum[j] = 0.f;
#pragma unroll
    for (int p = 0; p < 4; p++) {
        int r = row0 + ty * 8 + 2 * p;
        bool v0 = r < rend, v1 = (r + 1) < rend;
#pragma unroll
        for (int j = 0; j < 8; j++) {
            float2 v = u2f(acc[p][j]);
            if (v0) csum[j] += fmaxf(v.x + bv[j], 0.f);
            if (v1) csum[j] += fmaxf(v.y + bv[j], 0.f);
        }
    }
    __syncthreads();
#pragma unroll
    for (int j = 0; j < 8; j++) As[ty * 128 + tx * 8 + j] = csum[j];
    __syncthreads();
    if (tid < 128) {
        float s = 0.f;
#pragma unroll
        for (int t = 0; t < 16; t++) s += As[t * 128 + tid];
        atomicAdd(&g_psum[k * DH + col0 + tid], s);
    }
}

// ---------------- head: pooling -> fc -> gated attention -> rho -> classifier ----------------
__global__ __launch_bounds__(512) void k_head(const float* __restrict__ fc_W, const float* __restrict__ fc_b,
                                              const float* __restrict__ Va,   const float* __restrict__ ba,
                                              const float* __restrict__ Vb,   const float* __restrict__ bb,
                                              const float* __restrict__ Vc,   const float* __restrict__ bc,
                                              const float* __restrict__ rho_W, const float* __restrict__ rho_b,
                                              const float* __restrict__ cls_W, const float* __restrict__ cls_b,
                                              float* __restrict__ out, int out_size) {
    __shared__ float pooled_s[KC * DH];
    __shared__ float h_s[KC * DH];
    __shared__ float hpath[DH];
    __shared__ float hp2[DA];
    __shared__ float Alog[KC];
    __shared__ float attw[KC];
    __shared__ float logits_s[NCLS];

    int tid = threadIdx.x;

    for (int idx = tid; idx < KC * DH; idx += 512) {
        int k = idx / DH;
        int c = g_cnt[k];
        pooled_s[idx] = (c > 0) ? g_psum[idx] / (float)c : 0.f;
    }
    if (tid < KC) Alog[tid] = bc[0];
    if (tid < NCLS) logits_s[tid] = cls_b[tid];
    __syncthreads();

    {
        int j = tid;
        float acc[KC];
#pragma unroll
        for (int k = 0; k < KC; k++) acc[k] = fc_b[j];
        for (int i = 0; i < DH; i++) {
            float w = fc_W[i * DH + j];
#pragma unroll
            for (int k = 0; k < KC; k++) acc[k] += pooled_s[k * DH + i] * w;
        }
#pragma unroll
        for (int k = 0; k < KC; k++) h_s[k * DH + j] = fmaxf(acc[k], 0.f);
    }
    __syncthreads();

    if (tid < DA) {
        int m = tid;
        float aA[KC], aB[KC];
#pragma unroll
        for (int k = 0; k < KC; k++) { aA[k] = ba[m]; aB[k] = bb[m]; }
        for (int j = 0; j < DH; j++) {
            float va = Va[j * DA + m];
            float vb = Vb[j * DA + m];
#pragma unroll
            for (int k = 0; k < KC; k++) {
                float hv = h_s[k * DH + j];
                aA[k] += hv * va;
                aB[k] += hv * vb;
            }
        }
        float vc = Vc[m];
#pragma unroll
        for (int k = 0; k < KC; k++) {
            float contrib = tanhf(aA[k]) * (1.f / (1.f + expf(-aB[k]))) * vc;
            atomicAdd(&Alog[k], contrib);
        }
    }
    __syncthreads();

    if (tid == 0) {
        float mx = -1e30f;
        for (int k = 0; k < KC; k++) mx = fmaxf(mx, Alog[k]);
        float s = 0.f;
        for (int k = 0; k < KC; k++) { float e = expf(Alog[k] - mx); attw[k] = e; s += e; }
        float inv = 1.f / s;
        for (int k = 0; k < KC; k++) attw[k] *= inv;
    }
    __syncthreads();

    {
        int j = tid;
        float s = 0.f;
#pragma unroll
        for (int k = 0; k < KC; k++) s += attw[k] * h_s[k * DH + j];
        hpath[j] = s;
    }
    __syncthreads();

    if (tid < DA) {
        int m = tid;
        float acc = rho_b[m];
        for (int j = 0; j < DH; j++) acc += hpath[j] * rho_W[j * DA + m];
        hp2[m] = fmaxf(acc, 0.f);
    }
    __syncthreads();

    if (tid < DA) {
        int m = tid;
        float v = hp2[m];
#pragma unroll
        for (int c = 0; c < NCLS; c++) atomicAdd(&logits_s[c], v * cls_W[m * NCLS + c]);
    }
    __syncthreads();

    if (tid == 0) {
        float haz[NCLS], S[NCLS];
        float run = 1.f;
        int best = 0;
        float bval = logits_s[0];
        for (int c = 0; c < NCLS; c++) {
            if (logits_s[c] > bval) { bval = logits_s[c]; best = c; }
            haz[c] = 1.f / (1.f + expf(-logits_s[c]));
            run *= (1.f - haz[c]);
            S[c] = run;
        }
        float vals[9];
        for (int c = 0; c < NCLS; c++) vals[c] = haz[c];
        for (int c = 0; c < NCLS; c++) vals[NCLS + c] = S[c];
        vals[8] = (float)best;
        for (int i = 0; i < out_size; i++) out[i] = (i < 9) ? vals[i] : 0.f;
    }
}

// ---------------- launch ----------------
extern "C" void kernel_launch(void* const* d_in, const int* in_sizes, int n_in,
                              void* d_out, int out_size) {
    const float* x     = (const float*)d_in[0];
    const int*   cid   = (const int*)d_in[1];
    const float* W1    = (const float*)d_in[2];
    const float* b1    = (const float*)d_in[3];
    const float* W2    = (const float*)d_in[4];
    const float* b2    = (const float*)d_in[5];
    const float* fc_W  = (const float*)d_in[6];
    const float* fc_b  = (const float*)d_in[7];
    const float* Va    = (const float*)d_in[8];
    const float* ba    = (const float*)d_in[9];
    const float* Vb    = (const float*)d_in[10];
    const float* bb    = (const float*)d_in[11];
    const float* Vc    = (const float*)d_in[12];
    const float* bc    = (const float*)d_in[13];
    const float* rho_W = (const float*)d_in[14];
    const float* rho_b = (const float*)d_in[15];
    const float* cls_W = (const float*)d_in[16];
    const float* cls_b = (const float*)d_in[17];
    float* out = (float*)d_out;

    int n = in_sizes[0] / DIN;   // 8192

    k_init<<<32, 256>>>();
    k_hist<<<(n + 255) / 256, 256>>>(cid, n);
    k_offsets<<<1, 1>>>();
    k_scatter<<<(n + 255) / 256, 256>>>(cid, n);

    dim3 grid(DH / 128, (n + 127) / 128, KC);
    k_gemm1<<<grid, 256>>>(x, W1, b1);
    k_gemm2<<<grid, 256>>>(W2, b2);

    k_head<<<1, 512>>>(fc_W, fc_b, Va, ba, Vb, bb, Vc, bc,
                       rho_W, rho_b, cls_W, cls_b, out, out_size);
}

// round 6
// speedup vs baseline: 2.0264x; 2.0264x over previous
#include <cuda_runtime.h>
#include <cuda_bf16.h>
#include <math.h>
#include <stdint.h>

#define NPATCH 8192
#define NPAD   (NPATCH + 128)
#define KC     10
#define DIN    1024
#define DH     512
#define DA     256
#define NCLS   4

#define K1CAT (3 * DIN)   // 3072: [x_hi | x_hi | x_lo] vs [w_hi | w_lo | w_hi]
#define K2CAT (3 * DH)    // 1536

// ---------------- device scratch (ONLY referenced inside device code) ----------------
__device__ int   g_cnt[KC];
__device__ int   g_off[KC + 1];
__device__ int   g_cursor[KC];
__device__ int   g_order[NPATCH];
__device__ __align__(128) __nv_bfloat16 g_xcat [(size_t)NPAD * K1CAT];
__device__ __align__(128) __nv_bfloat16 g_w1cat[(size_t)KC * DH * K1CAT];
__device__ __align__(128) __nv_bfloat16 g_w2cat[(size_t)KC * DH * K2CAT];
__device__ __align__(128) __nv_bfloat16 g_h1cat[(size_t)NPAD * K2CAT];
__device__ float g_psum[KC * DH];

// ---------------- PTX helpers (legal on plain compute_103) ----------------
__device__ __forceinline__ uint32_t smem_u32(const void* p) {
    uint32_t a;
    asm("{ .reg .u64 t; cvta.to.shared.u64 t, %1; cvt.u32.u64 %0, t; }" : "=r"(a) : "l"(p));
    return a;
}
#define CPASYNC16(dst, src) asm volatile("cp.async.ca.shared.global [%0], [%1], 16;" :: "r"(dst), "l"(src) : "memory")
#define CP_COMMIT()         asm volatile("cp.async.commit_group;" ::: "memory")
#define CP_WAIT(n)          asm volatile("cp.async.wait_group %0;" :: "n"(n) : "memory")

__device__ __forceinline__ void ldsm4(uint32_t& r0, uint32_t& r1, uint32_t& r2, uint32_t& r3,
                                      uint32_t addr) {
    asm volatile("ldmatrix.sync.aligned.m8n8.x4.shared.b16 {%0,%1,%2,%3}, [%4];"
                 : "=r"(r0), "=r"(r1), "=r"(r2), "=r"(r3) : "r"(addr));
}
__device__ __forceinline__ void mma_bf16(float* c, uint32_t a0, uint32_t a1, uint32_t a2,
                                         uint32_t a3, uint32_t b0, uint32_t b1) {
    asm volatile("mma.sync.aligned.m16n8k16.row.col.f32.bf16.bf16.f32 "
                 "{%0,%1,%2,%3}, {%4,%5,%6,%7}, {%8,%9}, {%0,%1,%2,%3};"
                 : "+f"(c[0]), "+f"(c[1]), "+f"(c[2]), "+f"(c[3])
                 : "r"(a0), "r"(a1), "r"(a2), "r"(a3), "r"(b0), "r"(b1));
}

__device__ __forceinline__ void split1(float v, __nv_bfloat16& hi, __nv_bfloat16& lo) {
    hi = __float2bfloat16_rn(v);
    lo = __float2bfloat16_rn(v - __bfloat162float(hi));
}

// ---------------- setup kernels ----------------
__global__ void k_init() {
    int tid = blockIdx.x * blockDim.x + threadIdx.x;
    if (tid < KC) { g_cnt[tid] = 0; g_cursor[tid] = 0; }
    for (int i = tid; i < KC * DH; i += gridDim.x * blockDim.x) g_psum[i] = 0.f;
}
__global__ void k_hist(const int* __restrict__ cid, int n) {
    int i = blockIdx.x * blockDim.x + threadIdx.x;
    if (i < n) atomicAdd(&g_cnt[cid[i]], 1);
}
__global__ void k_offsets() {
    int s = 0; g_off[0] = 0;
    for (int k = 0; k < KC; k++) { s += g_cnt[k]; g_off[k + 1] = s; }
}
__global__ void k_scatter(const int* __restrict__ cid, int n) {
    int i = blockIdx.x * blockDim.x + threadIdx.x;
    if (i < n) {
        int c = cid[i];
        int pos = g_off[c] + atomicAdd(&g_cursor[c], 1);
        g_order[pos] = i;
    }
}

// gather + split x: row layout [hi(1024) | hi(1024) | lo(1024)]
__global__ void k_conv_x(const float* __restrict__ x) {
    int gid = blockIdx.x * 256 + threadIdx.x;  // NPATCH*128 threads
    int r = gid >> 7, c = gid & 127;
    const float* s = x + (size_t)g_order[r] * DIN + c * 8;
    float v[8];
    *(float4*)(v)     = *(const float4*)s;
    *(float4*)(v + 4) = *(const float4*)(s + 4);
    uint32_t hiw[4], low[4];
#pragma unroll
    for (int q = 0; q < 4; q++) {
        __nv_bfloat16 h0, l0, h1, l1;
        split1(v[2 * q], h0, l0);
        split1(v[2 * q + 1], h1, l1);
        __nv_bfloat162 hp(h0, h1), lp(l0, l1);
        hiw[q] = *(uint32_t*)&hp;
        low[q] = *(uint32_t*)&lp;
    }
    __nv_bfloat16* base = g_xcat + (size_t)r * K1CAT + c * 8;
    uint4 hv = make_uint4(hiw[0], hiw[1], hiw[2], hiw[3]);
    uint4 lv = make_uint4(low[0], low[1], low[2], low[3]);
    *(uint4*)(base)            = hv;
    *(uint4*)(base + DIN)      = hv;
    *(uint4*)(base + 2 * DIN)  = lv;
}

// transpose + split W[k][KD][DH] -> cat[k][DH][3*KD] = [hi | lo | hi]
// IS_W1 selects destination symbol INSIDE device code (never pass __device__ syms from host!)
template <int IS_W1>
__global__ void k_conv_w(const float* __restrict__ W) {
    const int KD = IS_W1 ? DIN : DH;
    __nv_bfloat16* out = IS_W1 ? g_w1cat : g_w2cat;
    __shared__ float t[32][33];
    int tx = threadIdx.x, ty = threadIdx.y;
    int kk0 = blockIdx.x * 32, n0 = blockIdx.y * 32, k = blockIdx.z;
    const float* src = W + (size_t)k * KD * DH;
#pragma unroll
    for (int i = 0; i < 4; i++) {
        int row = ty + i * 8;
        t[row][tx] = src[(size_t)(kk0 + row) * DH + n0 + tx];
    }
    __syncthreads();
    int KD3 = 3 * KD;
    __nv_bfloat16* dst = out + (size_t)k * DH * KD3;
#pragma unroll
    for (int i = 0; i < 4; i++) {
        int row = ty + i * 8;
        __nv_bfloat16 hi, lo;
        split1(t[tx][row], hi, lo);
        size_t base = (size_t)(n0 + row) * KD3 + kk0 + tx;
        dst[base]          = hi;
        dst[base + KD]     = lo;
        dst[base + 2 * KD] = hi;
    }
}

// ---------------- HMMA grouped GEMM, 128x128 CTA tile, BK=32, double-buffered cp.async ----
// EPI = 0: h1cat = split(relu(acc + bias)), A = g_xcat,  B = g_w1cat, KDIM = K1CAT
// EPI = 1: psum += colsum(relu(acc + bias)), A = g_h1cat, B = g_w2cat, KDIM = K2CAT
#define LDA 40   // padded smem row stride in bf16

template <int KDIM, int EPI>
__global__ __launch_bounds__(256) void k_mma(const float* __restrict__ bias) {
    const __nv_bfloat16* Asrc = (EPI == 0) ? g_xcat : g_h1cat;
    const __nv_bfloat16* Bsrc = (EPI == 0) ? g_w1cat : g_w2cat;

    int k = blockIdx.z;
    int rend = g_off[k + 1];
    int row0 = g_off[k] + blockIdx.y * 128;
    if (row0 >= rend) return;
    int col0 = blockIdx.x * 128;

    __shared__ __align__(16) __nv_bfloat16 sA[2][128 * LDA];
    __shared__ __align__(16) __nv_bfloat16 sB[2][128 * LDA];

    int tid = threadIdx.x;
    int wid = tid >> 5, lane = tid & 31;
    int warp_m = wid & 1;
    int warp_n = wid >> 1;

    float acc[4][4][4];
#pragma unroll
    for (int mf = 0; mf < 4; mf++)
#pragma unroll
        for (int nf = 0; nf < 4; nf++)
#pragma unroll
            for (int q = 0; q < 4; q++) acc[mf][nf][q] = 0.f;

    int lrow = tid >> 1, lhalf = tid & 1;
    uint32_t aSm[2] = {smem_u32(&sA[0][0]), smem_u32(&sA[1][0])};
    uint32_t bSm[2] = {smem_u32(&sB[0][0]), smem_u32(&sB[1][0])};
    uint32_t ldOff[2];
    const __nv_bfloat16* aSrcQ[2];
    const __nv_bfloat16* bSrcQ[2];
#pragma unroll
    for (int q = 0; q < 2; q++) {
        int seg = lhalf * 2 + q;
        ldOff[q] = (uint32_t)(lrow * LDA + seg * 8) * 2;
        aSrcQ[q] = Asrc + (size_t)(row0 + lrow) * KDIM + seg * 8;
        bSrcQ[q] = Bsrc + ((size_t)k * DH + col0 + lrow) * KDIM + seg * 8;
    }

    int lane15 = lane & 15, lanehi = lane >> 4;
    uint32_t offA[4], offB[2];
#pragma unroll
    for (int mf = 0; mf < 4; mf++)
        offA[mf] = (uint32_t)((warp_m * 64 + mf * 16 + lane15) * LDA + lanehi * 8) * 2;
#pragma unroll
    for (int ng = 0; ng < 2; ng++)
        offB[ng] = (uint32_t)((warp_n * 32 + ng * 16 + lane15) * LDA + lanehi * 8) * 2;

    const int NCH = KDIM / 32;

#pragma unroll
    for (int q = 0; q < 2; q++) {
        CPASYNC16(aSm[0] + ldOff[q], aSrcQ[q]);
        CPASYNC16(bSm[0] + ldOff[q], bSrcQ[q]);
    }
    CP_COMMIT();

    for (int s = 0; s < NCH; s++) {
        int buf = s & 1;
        if (s + 1 < NCH) {
            int nb = (s + 1) & 1;
#pragma unroll
            for (int q = 0; q < 2; q++) {
                CPASYNC16(aSm[nb] + ldOff[q], aSrcQ[q] + (size_t)(s + 1) * 32);
                CPASYNC16(bSm[nb] + ldOff[q], bSrcQ[q] + (size_t)(s + 1) * 32);
            }
            CP_COMMIT();
            CP_WAIT(1);
        } else {
            CP_WAIT(0);
        }
        __syncthreads();

#pragma unroll
        for (int ks = 0; ks < 2; ks++) {
            uint32_t kof = ks * 32;
            uint32_t afr[4][4], bfr[4][2];
#pragma unroll
            for (int mf = 0; mf < 4; mf++)
                ldsm4(afr[mf][0], afr[mf][1], afr[mf][2], afr[mf][3], aSm[buf] + offA[mf] + kof);
#pragma unroll
            for (int ng = 0; ng < 2; ng++) {
                uint32_t r0, r1, r2, r3;
                ldsm4(r0, r1, r2, r3, bSm[buf] + offB[ng] + kof);
                bfr[ng * 2 + 0][0] = r0; bfr[ng * 2 + 0][1] = r2;
                bfr[ng * 2 + 1][0] = r1; bfr[ng * 2 + 1][1] = r3;
            }
#pragma unroll
            for (int mf = 0; mf < 4; mf++)
#pragma unroll
                for (int nf = 0; nf < 4; nf++)
                    mma_bf16(acc[mf][nf], afr[mf][0], afr[mf][1], afr[mf][2], afr[mf][3],
                             bfr[nf][0], bfr[nf][1]);
        }
        __syncthreads();
    }

    // ---------------- epilogue ----------------
    const float* bp = bias + k * DH + col0 + warp_n * 32;
    float bv[4][2];
#pragma unroll
    for (int nf = 0; nf < 4; nf++) {
        bv[nf][0] = __ldg(bp + nf * 8 + (lane & 3) * 2);
        bv[nf][1] = __ldg(bp + nf * 8 + (lane & 3) * 2 + 1);
    }
    int rbase = row0 + warp_m * 64 + (lane >> 2);

    if (EPI == 0) {
#pragma unroll
        for (int mf = 0; mf < 4; mf++) {
#pragma unroll
            for (int half = 0; half < 2; half++) {
                int r = rbase + mf * 16 + half * 8;
                if (r >= rend) continue;
#pragma unroll
                for (int nf = 0; nf < 4; nf++) {
                    int c = col0 + warp_n * 32 + nf * 8 + (lane & 3) * 2;
                    float v0 = fmaxf(acc[mf][nf][half * 2 + 0] + bv[nf][0], 0.f);
                    float v1 = fmaxf(acc[mf][nf][half * 2 + 1] + bv[nf][1], 0.f);
                    __nv_bfloat16 h0, l0, h1, l1;
                    split1(v0, h0, l0);
                    split1(v1, h1, l1);
                    __nv_bfloat162 hp(h0, h1), lp(l0, l1);
                    __nv_bfloat16* base = g_h1cat + (size_t)r * K2CAT + c;
                    *(__nv_bfloat162*)(base)          = hp;
                    *(__nv_bfloat162*)(base + DH)     = hp;
                    *(__nv_bfloat162*)(base + 2 * DH) = lp;
                }
            }
        }
    } else {
#pragma unroll
        for (int nf = 0; nf < 4; nf++) {
            float s0 = 0.f, s1 = 0.f;
#pragma unroll
            for (int mf = 0; mf < 4; mf++) {
                int r0 = rbase + mf * 16;
                int r1 = r0 + 8;
                if (r0 < rend) {
                    s0 += fmaxf(acc[mf][nf][0] + bv[nf][0], 0.f);
                    s1 += fmaxf(acc[mf][nf][1] + bv[nf][1], 0.f);
                }
                if (r1 < rend) {
                    s0 += fmaxf(acc[mf][nf][2] + bv[nf][0], 0.f);
                    s1 += fmaxf(acc[mf][nf][3] + bv[nf][1], 0.f);
                }
            }
#pragma unroll
            for (int off = 16; off >= 4; off >>= 1) {
                s0 += __shfl_xor_sync(0xffffffffu, s0, off);
                s1 += __shfl_xor_sync(0xffffffffu, s1, off);
            }
            if (lane < 4) {
                int c = col0 + warp_n * 32 + nf * 8 + lane * 2;
                atomicAdd(&g_psum[k * DH + c], s0);
                atomicAdd(&g_psum[k * DH + c + 1], s1);
            }
        }
    }
}

// ---------------- head ----------------
__global__ __launch_bounds__(512) void k_head(const float* __restrict__ fc_W, const float* __restrict__ fc_b,
                                              const float* __restrict__ Va,   const float* __restrict__ ba,
                                              const float* __restrict__ Vb,   const float* __restrict__ bb,
                                              const float* __restrict__ Vc,   const float* __restrict__ bc,
                                              const float* __restrict__ rho_W, const float* __restrict__ rho_b,
                                              const float* __restrict__ cls_W, const float* __restrict__ cls_b,
                                              float* __restrict__ out, int out_size) {
    __shared__ float pooled_s[KC * DH];
    __shared__ float h_s[KC * DH];
    __shared__ float hpath[DH];
    __shared__ float hp2[DA];
    __shared__ float Alog[KC];
    __shared__ float attw[KC];
    __shared__ float logits_s[NCLS];

    int tid = threadIdx.x;

    for (int idx = tid; idx < KC * DH; idx += 512) {
        int k = idx / DH;
        int c = g_cnt[k];
        pooled_s[idx] = (c > 0) ? g_psum[idx] / (float)c : 0.f;
    }
    if (tid < KC) Alog[tid] = bc[0];
    if (tid < NCLS) logits_s[tid] = cls_b[tid];
    __syncthreads();

    {
        int j = tid;
        float acc[KC];
#pragma unroll
        for (int k = 0; k < KC; k++) acc[k] = fc_b[j];
        for (int i = 0; i < DH; i++) {
            float w = fc_W[i * DH + j];
#pragma unroll
            for (int k = 0; k < KC; k++) acc[k] += pooled_s[k * DH + i] * w;
        }
#pragma unroll
        for (int k = 0; k < KC; k++) h_s[k * DH + j] = fmaxf(acc[k], 0.f);
    }
    __syncthreads();

    if (tid < DA) {
        int m = tid;
        float aA[KC], aB[KC];
#pragma unroll
        for (int k = 0; k < KC; k++) { aA[k] = ba[m]; aB[k] = bb[m]; }
        for (int j = 0; j < DH; j++) {
            float va = Va[j * DA + m];
            float vb = Vb[j * DA + m];
#pragma unroll
            for (int k = 0; k < KC; k++) {
                float hv = h_s[k * DH + j];
                aA[k] += hv * va;
                aB[k] += hv * vb;
            }
        }
        float vc = Vc[m];
#pragma unroll
        for (int k = 0; k < KC; k++) {
            float contrib = tanhf(aA[k]) * (1.f / (1.f + expf(-aB[k]))) * vc;
            atomicAdd(&Alog[k], contrib);
        }
    }
    __syncthreads();

    if (tid == 0) {
        float mx = -1e30f;
        for (int k = 0; k < KC; k++) mx = fmaxf(mx, Alog[k]);
        float s = 0.f;
        for (int k = 0; k < KC; k++) { float e = expf(Alog[k] - mx); attw[k] = e; s += e; }
        float inv = 1.f / s;
        for (int k = 0; k < KC; k++) attw[k] *= inv;
    }
    __syncthreads();

    {
        int j = tid;
        float s = 0.f;
#pragma unroll
        for (int k = 0; k < KC; k++) s += attw[k] * h_s[k * DH + j];
        hpath[j] = s;
    }
    __syncthreads();

    if (tid < DA) {
        int m = tid;
        float acc = rho_b[m];
        for (int j = 0; j < DH; j++) acc += hpath[j] * rho_W[j * DA + m];
        hp2[m] = fmaxf(acc, 0.f);
    }
    __syncthreads();

    if (tid < DA) {
        int m = tid;
        float v = hp2[m];
#pragma unroll
        for (int c = 0; c < NCLS; c++) atomicAdd(&logits_s[c], v * cls_W[m * NCLS + c]);
    }
    __syncthreads();

    if (tid == 0) {
        float haz[NCLS], S[NCLS];
        float run = 1.f;
        int best = 0;
        float bval = logits_s[0];
        for (int c = 0; c < NCLS; c++) {
            if (logits_s[c] > bval) { bval = logits_s[c]; best = c; }
            haz[c] = 1.f / (1.f + expf(-logits_s[c]));
            run *= (1.f - haz[c]);
            S[c] = run;
        }
        float vals[9];
        for (int c = 0; c < NCLS; c++) vals[c] = haz[c];
        for (int c = 0; c < NCLS; c++) vals[NCLS + c] = S[c];
        vals[8] = (float)best;
        for (int i = 0; i < out_size; i++) out[i] = (i < 9) ? vals[i] : 0.f;
    }
}

// ---------------- launch ----------------
extern "C" void kernel_launch(void* const* d_in, const int* in_sizes, int n_in,
                              void* d_out, int out_size) {
    const float* x     = (const float*)d_in[0];
    const int*   cid   = (const int*)d_in[1];
    const float* W1    = (const float*)d_in[2];
    const float* b1    = (const float*)d_in[3];
    const float* W2    = (const float*)d_in[4];
    const float* b2    = (const float*)d_in[5];
    const float* fc_W  = (const float*)d_in[6];
    const float* fc_b  = (const float*)d_in[7];
    const float* Va    = (const float*)d_in[8];
    const float* ba    = (const float*)d_in[9];
    const float* Vb    = (const float*)d_in[10];
    const float* bb    = (const float*)d_in[11];
    const float* Vc    = (const float*)d_in[12];
    const float* bc    = (const float*)d_in[13];
    const float* rho_W = (const float*)d_in[14];
    const float* rho_b = (const float*)d_in[15];
    const float* cls_W = (const float*)d_in[16];
    const float* cls_b = (const float*)d_in[17];
    float* out = (float*)d_out;

    int n = in_sizes[0] / DIN;   // 8192

    k_init<<<32, 256>>>();
    k_hist<<<(n + 255) / 256, 256>>>(cid, n);
    k_offsets<<<1, 1>>>();
    k_scatter<<<(n + 255) / 256, 256>>>(cid, n);

    k_conv_x<<<(n * 128 + 255) / 256, 256>>>(x);
    {
        dim3 b(32, 8);
        k_conv_w<1><<<dim3(DIN / 32, DH / 32, KC), b>>>(W1);
        k_conv_w<0><<<dim3(DH / 32, DH / 32, KC), b>>>(W2);
    }

    dim3 grid(DH / 128, (n + 127) / 128, KC);
    k_mma<K1CAT, 0><<<grid, 256>>>(b1);
    k_mma<K2CAT, 1><<<grid, 256>>>(b2);

    k_head<<<1, 512>>>(fc_W, fc_b, Va, ba, Vb, bb, Vc, bc,
                       rho_W, rho_b, cls_W, cls_b, out, out_size);
}

// round 7
// speedup vs baseline: 2.5305x; 1.2488x over previous
#include <cuda_runtime.h>
#include <cuda_fp16.h>
#include <math.h>
#include <stdint.h>

#define NPATCH 8192
#define NPAD   (NPATCH + 128)
#define KC     10
#define DIN    1024
#define DH     512
#define DA     256
#define NCLS   4

// ---------------- device scratch (ONLY referenced inside device code) ----------------
__device__ int   g_cnt[KC];
__device__ int   g_off[KC + 1];
__device__ int   g_cursor[KC];
__device__ int   g_order[NPATCH];
__device__ __align__(128) __half g_xg [(size_t)NPAD * DIN];     // 16.8 MB
__device__ __align__(128) __half g_w1t[(size_t)KC * DH * DIN];  // 10.5 MB [k][n][kdim]
__device__ __align__(128) __half g_w2t[(size_t)KC * DH * DH];   // 5.2 MB
__device__ __align__(128) __half g_h1 [(size_t)NPAD * DH];      // 8.4 MB
__device__ float g_psum[KC * DH];

// ---------------- PTX helpers (legal on plain compute_103) ----------------
__device__ __forceinline__ uint32_t smem_u32(const void* p) {
    uint32_t a;
    asm("{ .reg .u64 t; cvta.to.shared.u64 t, %1; cvt.u32.u64 %0, t; }" : "=r"(a) : "l"(p));
    return a;
}
#define CPASYNC16(dst, src) asm volatile("cp.async.ca.shared.global [%0], [%1], 16;" :: "r"(dst), "l"(src) : "memory")
#define CP_COMMIT()         asm volatile("cp.async.commit_group;" ::: "memory")
#define CP_WAIT(n)          asm volatile("cp.async.wait_group %0;" :: "n"(n) : "memory")

__device__ __forceinline__ void ldsm4(uint32_t& r0, uint32_t& r1, uint32_t& r2, uint32_t& r3,
                                      uint32_t addr) {
    asm volatile("ldmatrix.sync.aligned.m8n8.x4.shared.b16 {%0,%1,%2,%3}, [%4];"
                 : "=r"(r0), "=r"(r1), "=r"(r2), "=r"(r3) : "r"(addr));
}
__device__ __forceinline__ void mma_f16(float* c, uint32_t a0, uint32_t a1, uint32_t a2,
                                        uint32_t a3, uint32_t b0, uint32_t b1) {
    asm volatile("mma.sync.aligned.m16n8k16.row.col.f32.f16.f16.f32 "
                 "{%0,%1,%2,%3}, {%4,%5,%6,%7}, {%8,%9}, {%0,%1,%2,%3};"
                 : "+f"(c[0]), "+f"(c[1]), "+f"(c[2]), "+f"(c[3])
                 : "r"(a0), "r"(a1), "r"(a2), "r"(a3), "r"(b0), "r"(b1));
}

// ---------------- setup kernels ----------------
__global__ void k_init() {
    int tid = blockIdx.x * blockDim.x + threadIdx.x;
    if (tid < KC) { g_cnt[tid] = 0; g_cursor[tid] = 0; }
    for (int i = tid; i < KC * DH; i += gridDim.x * blockDim.x) g_psum[i] = 0.f;
}
__global__ void k_hist(const int* __restrict__ cid, int n) {
    int i = blockIdx.x * blockDim.x + threadIdx.x;
    if (i < n) atomicAdd(&g_cnt[cid[i]], 1);
}
__global__ void k_offsets() {
    int s = 0; g_off[0] = 0;
    for (int k = 0; k < KC; k++) { s += g_cnt[k]; g_off[k + 1] = s; }
}
__global__ void k_scatter(const int* __restrict__ cid, int n) {
    int i = blockIdx.x * blockDim.x + threadIdx.x;
    if (i < n) {
        int c = cid[i];
        int pos = g_off[c] + atomicAdd(&g_cursor[c], 1);
        g_order[pos] = i;
    }
}

// gather + fp32->fp16 convert of x
__global__ void k_conv_x(const float* __restrict__ x) {
    int gid = blockIdx.x * 256 + threadIdx.x;  // NPATCH*128 threads
    int r = gid >> 7, c = gid & 127;
    const float* s = x + (size_t)g_order[r] * DIN + c * 8;
    float4 a = *(const float4*)s, b = *(const float4*)(s + 4);
    __half2 p0 = __floats2half2_rn(a.x, a.y);
    __half2 p1 = __floats2half2_rn(a.z, a.w);
    __half2 p2 = __floats2half2_rn(b.x, b.y);
    __half2 p3 = __floats2half2_rn(b.z, b.w);
    uint4 o;
    o.x = *(uint32_t*)&p0; o.y = *(uint32_t*)&p1; o.z = *(uint32_t*)&p2; o.w = *(uint32_t*)&p3;
    *(uint4*)(g_xg + (size_t)r * DIN + c * 8) = o;
}

// transpose + convert W[k][KD][DH] -> out[k][DH][KD]  (symbol selected in device code)
template <int IS_W1>
__global__ void k_conv_w(const float* __restrict__ W) {
    const int KD = IS_W1 ? DIN : DH;
    __half* out = IS_W1 ? g_w1t : g_w2t;
    __shared__ float t[32][33];
    int tx = threadIdx.x, ty = threadIdx.y;
    int kk0 = blockIdx.x * 32, n0 = blockIdx.y * 32, k = blockIdx.z;
    const float* src = W + (size_t)k * KD * DH;
#pragma unroll
    for (int i = 0; i < 4; i++) {
        int row = ty + i * 8;
        t[row][tx] = src[(size_t)(kk0 + row) * DH + n0 + tx];
    }
    __syncthreads();
    __half* dst = out + (size_t)k * DH * KD;
#pragma unroll
    for (int i = 0; i < 4; i++) {
        int row = ty + i * 8;
        dst[(size_t)(n0 + row) * KD + kk0 + tx] = __float2half_rn(t[tx][row]);
    }
}

// ---------------- HMMA grouped GEMM, 128x128 CTA tile, BK=32, double-buffered cp.async ----
// EPI = 0: g_h1 = fp16(relu(acc + bias)), A = g_xg,  B = g_w1t, KDIM = DIN
// EPI = 1: psum += colsum(relu(acc + bias)), A = g_h1, B = g_w2t, KDIM = DH
#define LDA 40   // padded smem row stride in halves

template <int KDIM, int EPI>
__global__ __launch_bounds__(256) void k_mma(const float* __restrict__ bias) {
    const __half* Asrc = (EPI == 0) ? g_xg : g_h1;
    const __half* Bsrc = (EPI == 0) ? g_w1t : g_w2t;

    int k = blockIdx.z;
    int rend = g_off[k + 1];
    int row0 = g_off[k] + blockIdx.y * 128;
    if (row0 >= rend) return;
    int col0 = blockIdx.x * 128;

    __shared__ __align__(16) __half sA[2][128 * LDA];
    __shared__ __align__(16) __half sB[2][128 * LDA];

    int tid = threadIdx.x;
    int wid = tid >> 5, lane = tid & 31;
    int warp_m = wid & 1;
    int warp_n = wid >> 1;

    float acc[4][4][4];
#pragma unroll
    for (int mf = 0; mf < 4; mf++)
#pragma unroll
        for (int nf = 0; nf < 4; nf++)
#pragma unroll
            for (int q = 0; q < 4; q++) acc[mf][nf][q] = 0.f;

    int lrow = tid >> 1, lhalf = tid & 1;
    uint32_t aSm[2] = {smem_u32(&sA[0][0]), smem_u32(&sA[1][0])};
    uint32_t bSm[2] = {smem_u32(&sB[0][0]), smem_u32(&sB[1][0])};
    uint32_t ldOff[2];
    const __half* aSrcQ[2];
    const __half* bSrcQ[2];
#pragma unroll
    for (int q = 0; q < 2; q++) {
        int seg = lhalf * 2 + q;
        ldOff[q] = (uint32_t)(lrow * LDA + seg * 8) * 2;
        aSrcQ[q] = Asrc + (size_t)(row0 + lrow) * KDIM + seg * 8;
        bSrcQ[q] = Bsrc + ((size_t)k * DH + col0 + lrow) * KDIM + seg * 8;
    }

    int lane15 = lane & 15, lanehi = lane >> 4;
    uint32_t offA[4], offB[2];
#pragma unroll
    for (int mf = 0; mf < 4; mf++)
        offA[mf] = (uint32_t)((warp_m * 64 + mf * 16 + lane15) * LDA + lanehi * 8) * 2;
#pragma unroll
    for (int ng = 0; ng < 2; ng++)
        offB[ng] = (uint32_t)((warp_n * 32 + ng * 16 + lane15) * LDA + lanehi * 8) * 2;

    const int NCH = KDIM / 32;

#pragma unroll
    for (int q = 0; q < 2; q++) {
        CPASYNC16(aSm[0] + ldOff[q], aSrcQ[q]);
        CPASYNC16(bSm[0] + ldOff[q], bSrcQ[q]);
    }
    CP_COMMIT();

    for (int s = 0; s < NCH; s++) {
        int buf = s & 1;
        if (s + 1 < NCH) {
            int nb = (s + 1) & 1;
#pragma unroll
            for (int q = 0; q < 2; q++) {
                CPASYNC16(aSm[nb] + ldOff[q], aSrcQ[q] + (size_t)(s + 1) * 32);
                CPASYNC16(bSm[nb] + ldOff[q], bSrcQ[q] + (size_t)(s + 1) * 32);
            }
            CP_COMMIT();
            CP_WAIT(1);
        } else {
            CP_WAIT(0);
        }
        __syncthreads();

#pragma unroll
        for (int ks = 0; ks < 2; ks++) {
            uint32_t kof = ks * 32;
            uint32_t afr[4][4], bfr[4][2];
#pragma unroll
            for (int mf = 0; mf < 4; mf++)
                ldsm4(afr[mf][0], afr[mf][1], afr[mf][2], afr[mf][3], aSm[buf] + offA[mf] + kof);
#pragma unroll
            for (int ng = 0; ng < 2; ng++) {
                uint32_t r0, r1, r2, r3;
                ldsm4(r0, r1, r2, r3, bSm[buf] + offB[ng] + kof);
                bfr[ng * 2 + 0][0] = r0; bfr[ng * 2 + 0][1] = r2;
                bfr[ng * 2 + 1][0] = r1; bfr[ng * 2 + 1][1] = r3;
            }
#pragma unroll
            for (int mf = 0; mf < 4; mf++)
#pragma unroll
                for (int nf = 0; nf < 4; nf++)
                    mma_f16(acc[mf][nf], afr[mf][0], afr[mf][1], afr[mf][2], afr[mf][3],
                            bfr[nf][0], bfr[nf][1]);
        }
        __syncthreads();
    }

    // ---------------- epilogue ----------------
    const float* bp = bias + k * DH + col0 + warp_n * 32;
    float bv[4][2];
#pragma unroll
    for (int nf = 0; nf < 4; nf++) {
        bv[nf][0] = __ldg(bp + nf * 8 + (lane & 3) * 2);
        bv[nf][1] = __ldg(bp + nf * 8 + (lane & 3) * 2 + 1);
    }
    int rbase = row0 + warp_m * 64 + (lane >> 2);

    if (EPI == 0) {
#pragma unroll
        for (int mf = 0; mf < 4; mf++) {
#pragma unroll
            for (int half = 0; half < 2; half++) {
                int r = rbase + mf * 16 + half * 8;
                if (r >= rend) continue;
#pragma unroll
                for (int nf = 0; nf < 4; nf++) {
                    int c = col0 + warp_n * 32 + nf * 8 + (lane & 3) * 2;
                    float v0 = fmaxf(acc[mf][nf][half * 2 + 0] + bv[nf][0], 0.f);
                    float v1 = fmaxf(acc[mf][nf][half * 2 + 1] + bv[nf][1], 0.f);
                    *(__half2*)(g_h1 + (size_t)r * DH + c) = __floats2half2_rn(v0, v1);
                }
            }
        }
    } else {
#pragma unroll
        for (int nf = 0; nf < 4; nf++) {
            float s0 = 0.f, s1 = 0.f;
#pragma unroll
            for (int mf = 0; mf < 4; mf++) {
                int r0 = rbase + mf * 16;
                int r1 = r0 + 8;
                if (r0 < rend) {
                    s0 += fmaxf(acc[mf][nf][0] + bv[nf][0], 0.f);
                    s1 += fmaxf(acc[mf][nf][1] + bv[nf][1], 0.f);
                }
                if (r1 < rend) {
                    s0 += fmaxf(acc[mf][nf][2] + bv[nf][0], 0.f);
                    s1 += fmaxf(acc[mf][nf][3] + bv[nf][1], 0.f);
                }
            }
#pragma unroll
            for (int off = 16; off >= 4; off >>= 1) {
                s0 += __shfl_xor_sync(0xffffffffu, s0, off);
                s1 += __shfl_xor_sync(0xffffffffu, s1, off);
            }
            if (lane < 4) {
                int c = col0 + warp_n * 32 + nf * 8 + lane * 2;
                atomicAdd(&g_psum[k * DH + c], s0);
                atomicAdd(&g_psum[k * DH + c + 1], s1);
            }
        }
    }
}

// ---------------- head ----------------
__global__ __launch_bounds__(512) void k_head(const float* __restrict__ fc_W, const float* __restrict__ fc_b,
                                              const float* __restrict__ Va,   const float* __restrict__ ba,
                                              const float* __restrict__ Vb,   const float* __restrict__ bb,
                                              const float* __restrict__ Vc,   const float* __restrict__ bc,
                                              const float* __restrict__ rho_W, const float* __restrict__ rho_b,
                                              const float* __restrict__ cls_W, const float* __restrict__ cls_b,
                                              float* __restrict__ out, int out_size) {
    __shared__ float pooled_s[KC * DH];
    __shared__ float h_s[KC * DH];
    __shared__ float hpath[DH];
    __shared__ float hp2[DA];
    __shared__ float Alog[KC];
    __shared__ float attw[KC];
    __shared__ float logits_s[NCLS];

    int tid = threadIdx.x;

    for (int idx = tid; idx < KC * DH; idx += 512) {
        int k = idx / DH;
        int c = g_cnt[k];
        pooled_s[idx] = (c > 0) ? g_psum[idx] / (float)c : 0.f;
    }
    if (tid < KC) Alog[tid] = bc[0];
    if (tid < NCLS) logits_s[tid] = cls_b[tid];
    __syncthreads();

    {
        int j = tid;
        float acc[KC];
#pragma unroll
        for (int k = 0; k < KC; k++) acc[k] = fc_b[j];
        for (int i = 0; i < DH; i++) {
            float w = fc_W[i * DH + j];
#pragma unroll
            for (int k = 0; k < KC; k++) acc[k] += pooled_s[k * DH + i] * w;
        }
#pragma unroll
        for (int k = 0; k < KC; k++) h_s[k * DH + j] = fmaxf(acc[k], 0.f);
    }
    __syncthreads();

    if (tid < DA) {
        int m = tid;
        float aA[KC], aB[KC];
#pragma unroll
        for (int k = 0; k < KC; k++) { aA[k] = ba[m]; aB[k] = bb[m]; }
        for (int j = 0; j < DH; j++) {
            float va = Va[j * DA + m];
            float vb = Vb[j * DA + m];
#pragma unroll
            for (int k = 0; k < KC; k++) {
                float hv = h_s[k * DH + j];
                aA[k] += hv * va;
                aB[k] += hv * vb;
            }
        }
        float vc = Vc[m];
#pragma unroll
        for (int k = 0; k < KC; k++) {
            float contrib = tanhf(aA[k]) * (1.f / (1.f + expf(-aB[k]))) * vc;
            atomicAdd(&Alog[k], contrib);
        }
    }
    __syncthreads();

    if (tid == 0) {
        float mx = -1e30f;
        for (int k = 0; k < KC; k++) mx = fmaxf(mx, Alog[k]);
        float s = 0.f;
        for (int k = 0; k < KC; k++) { float e = expf(Alog[k] - mx); attw[k] = e; s += e; }
        float inv = 1.f / s;
        for (int k = 0; k < KC; k++) attw[k] *= inv;
    }
    __syncthreads();

    {
        int j = tid;
        float s = 0.f;
#pragma unroll
        for (int k = 0; k < KC; k++) s += attw[k] * h_s[k * DH + j];
        hpath[j] = s;
    }
    __syncthreads();

    if (tid < DA) {
        int m = tid;
        float acc = rho_b[m];
        for (int j = 0; j < DH; j++) acc += hpath[j] * rho_W[j * DA + m];
        hp2[m] = fmaxf(acc, 0.f);
    }
    __syncthreads();

    if (tid < DA) {
        int m = tid;
        float v = hp2[m];
#pragma unroll
        for (int c = 0; c < NCLS; c++) atomicAdd(&logits_s[c], v * cls_W[m * NCLS + c]);
    }
    __syncthreads();

    if (tid == 0) {
        float haz[NCLS], S[NCLS];
        float run = 1.f;
        int best = 0;
        float bval = logits_s[0];
        for (int c = 0; c < NCLS; c++) {
            if (logits_s[c] > bval) { bval = logits_s[c]; best = c; }
            haz[c] = 1.f / (1.f + expf(-logits_s[c]));
            run *= (1.f - haz[c]);
            S[c] = run;
        }
        float vals[9];
        for (int c = 0; c < NCLS; c++) vals[c] = haz[c];
        for (int c = 0; c < NCLS; c++) vals[NCLS + c] = S[c];
        vals[8] = (float)best;
        for (int i = 0; i < out_size; i++) out[i] = (i < 9) ? vals[i] : 0.f;
    }
}

// ---------------- launch ----------------
extern "C" void kernel_launch(void* const* d_in, const int* in_sizes, int n_in,
                              void* d_out, int out_size) {
    const float* x     = (const float*)d_in[0];
    const int*   cid   = (const int*)d_in[1];
    const float* W1    = (const float*)d_in[2];
    const float* b1    = (const float*)d_in[3];
    const float* W2    = (const float*)d_in[4];
    const float* b2    = (const float*)d_in[5];
    const float* fc_W  = (const float*)d_in[6];
    const float* fc_b  = (const float*)d_in[7];
    const float* Va    = (const float*)d_in[8];
    const float* ba    = (const float*)d_in[9];
    const float* Vb    = (const float*)d_in[10];
    const float* bb    = (const float*)d_in[11];
    const float* Vc    = (const float*)d_in[12];
    const float* bc    = (const float*)d_in[13];
    const float* rho_W = (const float*)d_in[14];
    const float* rho_b = (const float*)d_in[15];
    const float* cls_W = (const float*)d_in[16];
    const float* cls_b = (const float*)d_in[17];
    float* out = (float*)d_out;

    int n = in_sizes[0] / DIN;   // 8192

    k_init<<<32, 256>>>();
    k_hist<<<(n + 255) / 256, 256>>>(cid, n);
    k_offsets<<<1, 1>>>();
    k_scatter<<<(n + 255) / 256, 256>>>(cid, n);

    k_conv_x<<<(n * 128 + 255) / 256, 256>>>(x);
    {
        dim3 b(32, 8);
        k_conv_w<1><<<dim3(DIN / 32, DH / 32, KC), b>>>(W1);
        k_conv_w<0><<<dim3(DH / 32, DH / 32, KC), b>>>(W2);
    }

    dim3 grid(DH / 128, (n + 127) / 128, KC);
    k_mma<DIN, 0><<<grid, 256>>>(b1);
    k_mma<DH, 1><<<grid, 256>>>(b2);

    k_head<<<1, 512>>>(fc_W, fc_b, Va, ba, Vb, bb, Vc, bc,
                       rho_W, rho_b, cls_W, cls_b, out, out_size);
}

// round 8
// speedup vs baseline: 8.4248x; 3.3293x over previous
#include <cuda_runtime.h>
#include <cuda_fp16.h>
#include <math.h>
#include <stdint.h>

#define NPATCH 8192
#define NPAD   (NPATCH + 128)
#define KC     10
#define DIN    1024
#define DH     512
#define DA     256
#define NCLS   4

// ---------------- device scratch (ONLY referenced inside device code) ----------------
__device__ int   g_cnt[KC];
__device__ int   g_off[KC + 1];
__device__ int   g_cursor[KC];
__device__ int   g_order[NPATCH];
__device__ __align__(128) __half g_xg [(size_t)NPAD * DIN];
__device__ __align__(128) __half g_w1t[(size_t)KC * DH * DIN];
__device__ __align__(128) __half g_w2t[(size_t)KC * DH * DH];
__device__ __align__(128) __half g_h1 [(size_t)NPAD * DH];
__device__ float g_psum[KC * DH];
__device__ float g_pooled[KC * DH];
__device__ float g_hs[KC * DH];
__device__ float g_Alog[KC];

// ---------------- PTX helpers ----------------
__device__ __forceinline__ uint32_t smem_u32(const void* p) {
    uint32_t a;
    asm("{ .reg .u64 t; cvta.to.shared.u64 t, %1; cvt.u32.u64 %0, t; }" : "=r"(a) : "l"(p));
    return a;
}
#define CPASYNC16(dst, src) asm volatile("cp.async.ca.shared.global [%0], [%1], 16;" :: "r"(dst), "l"(src) : "memory")
#define CP_COMMIT()         asm volatile("cp.async.commit_group;" ::: "memory")
#define CP_WAIT(n)          asm volatile("cp.async.wait_group %0;" :: "n"(n) : "memory")

__device__ __forceinline__ void ldsm4(uint32_t& r0, uint32_t& r1, uint32_t& r2, uint32_t& r3,
                                      uint32_t addr) {
    asm volatile("ldmatrix.sync.aligned.m8n8.x4.shared.b16 {%0,%1,%2,%3}, [%4];"
                 : "=r"(r0), "=r"(r1), "=r"(r2), "=r"(r3) : "r"(addr));
}
__device__ __forceinline__ void mma_f16(float* c, uint32_t a0, uint32_t a1, uint32_t a2,
                                        uint32_t a3, uint32_t b0, uint32_t b1) {
    asm volatile("mma.sync.aligned.m16n8k16.row.col.f32.f16.f16.f32 "
                 "{%0,%1,%2,%3}, {%4,%5,%6,%7}, {%8,%9}, {%0,%1,%2,%3};"
                 : "+f"(c[0]), "+f"(c[1]), "+f"(c[2]), "+f"(c[3])
                 : "r"(a0), "r"(a1), "r"(a2), "r"(a3), "r"(b0), "r"(b1));
}

// ---------------- setup kernels ----------------
__global__ void k_init() {
    int tid = blockIdx.x * blockDim.x + threadIdx.x;
    if (tid < KC) { g_cnt[tid] = 0; g_cursor[tid] = 0; }
    for (int i = tid; i < KC * DH; i += gridDim.x * blockDim.x) g_psum[i] = 0.f;
}
__global__ void k_hist(const int* __restrict__ cid, int n) {
    int i = blockIdx.x * blockDim.x + threadIdx.x;
    if (i < n) atomicAdd(&g_cnt[cid[i]], 1);
}
__global__ void k_offsets() {
    int s = 0; g_off[0] = 0;
    for (int k = 0; k < KC; k++) { s += g_cnt[k]; g_off[k + 1] = s; }
}
__global__ void k_scatter(const int* __restrict__ cid, int n) {
    int i = blockIdx.x * blockDim.x + threadIdx.x;
    if (i < n) {
        int c = cid[i];
        int pos = g_off[c] + atomicAdd(&g_cursor[c], 1);
        g_order[pos] = i;
    }
}

// gather + fp32->fp16 convert of x
__global__ void k_conv_x(const float* __restrict__ x) {
    int gid = blockIdx.x * 256 + threadIdx.x;
    int r = gid >> 7, c = gid & 127;
    const float* s = x + (size_t)g_order[r] * DIN + c * 8;
    float4 a = *(const float4*)s, b = *(const float4*)(s + 4);
    __half2 p0 = __floats2half2_rn(a.x, a.y);
    __half2 p1 = __floats2half2_rn(a.z, a.w);
    __half2 p2 = __floats2half2_rn(b.x, b.y);
    __half2 p3 = __floats2half2_rn(b.z, b.w);
    uint4 o;
    o.x = *(uint32_t*)&p0; o.y = *(uint32_t*)&p1; o.z = *(uint32_t*)&p2; o.w = *(uint32_t*)&p3;
    *(uint4*)(g_xg + (size_t)r * DIN + c * 8) = o;
}

// transpose + convert W[k][KD][DH] -> out[k][DH][KD]
template <int IS_W1>
__global__ void k_conv_w(const float* __restrict__ W) {
    const int KD = IS_W1 ? DIN : DH;
    __half* out = IS_W1 ? g_w1t : g_w2t;
    __shared__ float t[32][33];
    int tx = threadIdx.x, ty = threadIdx.y;
    int kk0 = blockIdx.x * 32, n0 = blockIdx.y * 32, k = blockIdx.z;
    const float* src = W + (size_t)k * KD * DH;
#pragma unroll
    for (int i = 0; i < 4; i++) {
        int row = ty + i * 8;
        t[row][tx] = src[(size_t)(kk0 + row) * DH + n0 + tx];
    }
    __syncthreads();
    __half* dst = out + (size_t)k * DH * KD;
#pragma unroll
    for (int i = 0; i < 4; i++) {
        int row = ty + i * 8;
        dst[(size_t)(n0 + row) * KD + kk0 + tx] = __float2half_rn(t[tx][row]);
    }
}

// ---------------- HMMA grouped GEMM (unchanged from passing R7) ----------------
#define LDA 40

template <int KDIM, int EPI>
__global__ __launch_bounds__(256) void k_mma(const float* __restrict__ bias) {
    const __half* Asrc = (EPI == 0) ? g_xg : g_h1;
    const __half* Bsrc = (EPI == 0) ? g_w1t : g_w2t;

    int k = blockIdx.z;
    int rend = g_off[k + 1];
    int row0 = g_off[k] + blockIdx.y * 128;
    if (row0 >= rend) return;
    int col0 = blockIdx.x * 128;

    __shared__ __align__(16) __half sA[2][128 * LDA];
    __shared__ __align__(16) __half sB[2][128 * LDA];

    int tid = threadIdx.x;
    int wid = tid >> 5, lane = tid & 31;
    int warp_m = wid & 1;
    int warp_n = wid >> 1;

    float acc[4][4][4];
#pragma unroll
    for (int mf = 0; mf < 4; mf++)
#pragma unroll
        for (int nf = 0; nf < 4; nf++)
#pragma unroll
            for (int q = 0; q < 4; q++) acc[mf][nf][q] = 0.f;

    int lrow = tid >> 1, lhalf = tid & 1;
    uint32_t aSm[2] = {smem_u32(&sA[0][0]), smem_u32(&sA[1][0])};
    uint32_t bSm[2] = {smem_u32(&sB[0][0]), smem_u32(&sB[1][0])};
    uint32_t ldOff[2];
    const __half* aSrcQ[2];
    const __half* bSrcQ[2];
#pragma unroll
    for (int q = 0; q < 2; q++) {
        int seg = lhalf * 2 + q;
        ldOff[q] = (uint32_t)(lrow * LDA + seg * 8) * 2;
        aSrcQ[q] = Asrc + (size_t)(row0 + lrow) * KDIM + seg * 8;
        bSrcQ[q] = Bsrc + ((size_t)k * DH + col0 + lrow) * KDIM + seg * 8;
    }

    int lane15 = lane & 15, lanehi = lane >> 4;
    uint32_t offA[4], offB[2];
#pragma unroll
    for (int mf = 0; mf < 4; mf++)
        offA[mf] = (uint32_t)((warp_m * 64 + mf * 16 + lane15) * LDA + lanehi * 8) * 2;
#pragma unroll
    for (int ng = 0; ng < 2; ng++)
        offB[ng] = (uint32_t)((warp_n * 32 + ng * 16 + lane15) * LDA + lanehi * 8) * 2;

    const int NCH = KDIM / 32;

#pragma unroll
    for (int q = 0; q < 2; q++) {
        CPASYNC16(aSm[0] + ldOff[q], aSrcQ[q]);
        CPASYNC16(bSm[0] + ldOff[q], bSrcQ[q]);
    }
    CP_COMMIT();

    for (int s = 0; s < NCH; s++) {
        int buf = s & 1;
        if (s + 1 < NCH) {
            int nb = (s + 1) & 1;
#pragma unroll
            for (int q = 0; q < 2; q++) {
                CPASYNC16(aSm[nb] + ldOff[q], aSrcQ[q] + (size_t)(s + 1) * 32);
                CPASYNC16(bSm[nb] + ldOff[q], bSrcQ[q] + (size_t)(s + 1) * 32);
            }
            CP_COMMIT();
            CP_WAIT(1);
        } else {
            CP_WAIT(0);
        }
        __syncthreads();

#pragma unroll
        for (int ks = 0; ks < 2; ks++) {
            uint32_t kof = ks * 32;
            uint32_t afr[4][4], bfr[4][2];
#pragma unroll
            for (int mf = 0; mf < 4; mf++)
                ldsm4(afr[mf][0], afr[mf][1], afr[mf][2], afr[mf][3], aSm[buf] + offA[mf] + kof);
#pragma unroll
            for (int ng = 0; ng < 2; ng++) {
                uint32_t r0, r1, r2, r3;
                ldsm4(r0, r1, r2, r3, bSm[buf] + offB[ng] + kof);
                bfr[ng * 2 + 0][0] = r0; bfr[ng * 2 + 0][1] = r2;
                bfr[ng * 2 + 1][0] = r1; bfr[ng * 2 + 1][1] = r3;
            }
#pragma unroll
            for (int mf = 0; mf < 4; mf++)
#pragma unroll
                for (int nf = 0; nf < 4; nf++)
                    mma_f16(acc[mf][nf], afr[mf][0], afr[mf][1], afr[mf][2], afr[mf][3],
                            bfr[nf][0], bfr[nf][1]);
        }
        __syncthreads();
    }

    const float* bp = bias + k * DH + col0 + warp_n * 32;
    float bv[4][2];
#pragma unroll
    for (int nf = 0; nf < 4; nf++) {
        bv[nf][0] = __ldg(bp + nf * 8 + (lane & 3) * 2);
        bv[nf][1] = __ldg(bp + nf * 8 + (lane & 3) * 2 + 1);
    }
    int rbase = row0 + warp_m * 64 + (lane >> 2);

    if (EPI == 0) {
#pragma unroll
        for (int mf = 0; mf < 4; mf++) {
#pragma unroll
            for (int half = 0; half < 2; half++) {
                int r = rbase + mf * 16 + half * 8;
                if (r >= rend) continue;
#pragma unroll
                for (int nf = 0; nf < 4; nf++) {
                    int c = col0 + warp_n * 32 + nf * 8 + (lane & 3) * 2;
                    float v0 = fmaxf(acc[mf][nf][half * 2 + 0] + bv[nf][0], 0.f);
                    float v1 = fmaxf(acc[mf][nf][half * 2 + 1] + bv[nf][1], 0.f);
                    *(__half2*)(g_h1 + (size_t)r * DH + c) = __floats2half2_rn(v0, v1);
                }
            }
        }
    } else {
#pragma unroll
        for (int nf = 0; nf < 4; nf++) {
            float s0 = 0.f, s1 = 0.f;
#pragma unroll
            for (int mf = 0; mf < 4; mf++) {
                int r0 = rbase + mf * 16;
                int r1 = r0 + 8;
                if (r0 < rend) {
                    s0 += fmaxf(acc[mf][nf][0] + bv[nf][0], 0.f);
                    s1 += fmaxf(acc[mf][nf][1] + bv[nf][1], 0.f);
                }
                if (r1 < rend) {
                    s0 += fmaxf(acc[mf][nf][2] + bv[nf][0], 0.f);
                    s1 += fmaxf(acc[mf][nf][3] + bv[nf][1], 0.f);
                }
            }
#pragma unroll
            for (int off = 16; off >= 4; off >>= 1) {
                s0 += __shfl_xor_sync(0xffffffffu, s0, off);
                s1 += __shfl_xor_sync(0xffffffffu, s1, off);
            }
            if (lane < 4) {
                int c = col0 + warp_n * 32 + nf * 8 + lane * 2;
                atomicAdd(&g_psum[k * DH + c], s0);
                atomicAdd(&g_psum[k * DH + c + 1], s1);
            }
        }
    }
}

// ---------------- parallel head ----------------
// pool: pooled = psum / cnt (0 if empty); also init Alog with bc
__global__ void k_pool(const float* __restrict__ bc) {
    int idx = blockIdx.x * 256 + threadIdx.x;
    if (idx < KC * DH) {
        int k = idx / DH;
        int c = g_cnt[k];
        g_pooled[idx] = (c > 0) ? g_psum[idx] / (float)c : 0.f;
    }
    if (idx < KC) g_Alog[idx] = bc[0];
}

// h = relu(pooled @ fc_W + fc_b): warp per output (k, j); 5120 outputs
__global__ __launch_bounds__(256) void k_headB(const float* __restrict__ fc_W,
                                               const float* __restrict__ fc_b) {
    int wid = (blockIdx.x * 256 + threadIdx.x) >> 5;
    int lane = threadIdx.x & 31;
    if (wid >= KC * DH) return;
    int k = wid / DH, j = wid % DH;
    const float* pr = g_pooled + k * DH;
    float s = 0.f;
#pragma unroll
    for (int t = 0; t < DH / 32; t++) {
        int i = t * 32 + lane;
        s += pr[i] * __ldg(fc_W + (size_t)i * DH + j);
    }
#pragma unroll
    for (int off = 16; off > 0; off >>= 1) s += __shfl_xor_sync(0xffffffffu, s, off);
    if (lane == 0) g_hs[k * DH + j] = fmaxf(s + __ldg(fc_b + j), 0.f);
}

// gated attention logits: warp per output (k, m); 2560 outputs
__global__ __launch_bounds__(256) void k_headC(const float* __restrict__ Va, const float* __restrict__ ba,
                                               const float* __restrict__ Vb, const float* __restrict__ bb,
                                               const float* __restrict__ Vc) {
    int wid = (blockIdx.x * 256 + threadIdx.x) >> 5;
    int lane = threadIdx.x & 31;
    if (wid >= KC * DA) return;
    int k = wid / DA, m = wid % DA;
    const float* hr = g_hs + k * DH;
    float sa = 0.f, sb = 0.f;
#pragma unroll
    for (int t = 0; t < DH / 32; t++) {
        int j = t * 32 + lane;
        float hv = hr[j];
        sa += hv * __ldg(Va + (size_t)j * DA + m);
        sb += hv * __ldg(Vb + (size_t)j * DA + m);
    }
#pragma unroll
    for (int off = 16; off > 0; off >>= 1) {
        sa += __shfl_xor_sync(0xffffffffu, sa, off);
        sb += __shfl_xor_sync(0xffffffffu, sb, off);
    }
    if (lane == 0) {
        float contrib = tanhf(sa + __ldg(ba + m)) * (1.f / (1.f + expf(-(sb + __ldg(bb + m))))) * __ldg(Vc + m);
        atomicAdd(&g_Alog[k], contrib);
    }
}

// tail: softmax over K, attention pool, rho, classifier, output
__global__ __launch_bounds__(512) void k_tail(const float* __restrict__ rho_W, const float* __restrict__ rho_b,
                                              const float* __restrict__ cls_W, const float* __restrict__ cls_b,
                                              float* __restrict__ out, int out_size) {
    __shared__ float attw[KC];
    __shared__ float hpath[DH];
    __shared__ float part[2][DA];
    __shared__ float hp2[DA];
    __shared__ float logits_s[NCLS];
    int tid = threadIdx.x;

    if (tid == 0) {
        float mx = -1e30f;
        float al[KC];
        for (int k = 0; k < KC; k++) { al[k] = g_Alog[k]; mx = fmaxf(mx, al[k]); }
        float s = 0.f;
        for (int k = 0; k < KC; k++) { float e = expf(al[k] - mx); attw[k] = e; s += e; }
        float inv = 1.f / s;
        for (int k = 0; k < KC; k++) attw[k] *= inv;
    }
    __syncthreads();

    {   // h_path
        float s = 0.f;
#pragma unroll
        for (int k = 0; k < KC; k++) s += attw[k] * g_hs[k * DH + tid];
        hpath[tid] = s;
    }
    __syncthreads();

    {   // rho: hp2 = relu(hpath @ rho_W + rho_b), split j-range over 2 halves
        int m = tid & 255, half = tid >> 8;
        float s = 0.f;
#pragma unroll 8
        for (int j = half * 256; j < half * 256 + 256; j++)
            s += hpath[j] * __ldg(rho_W + (size_t)j * DA + m);
        part[half][m] = s;
    }
    __syncthreads();
    if (tid < DA) hp2[tid] = fmaxf(part[0][tid] + part[1][tid] + __ldg(rho_b + tid), 0.f);
    __syncthreads();

    if (tid < 128) {   // classifier: warp c computes logit c
        int c = tid >> 5, lane = tid & 31;
        float s = 0.f;
#pragma unroll
        for (int t = 0; t < DA / 32; t++) {
            int m = t * 32 + lane;
            s += hp2[m] * __ldg(cls_W + m * NCLS + c);
        }
#pragma unroll
        for (int off = 16; off > 0; off >>= 1) s += __shfl_xor_sync(0xffffffffu, s, off);
        if (lane == 0) logits_s[c] = s + __ldg(cls_b + c);
    }
    __syncthreads();

    if (tid == 0) {
        float haz[NCLS], S[NCLS];
        float run = 1.f;
        int best = 0;
        float bval = logits_s[0];
        for (int c = 0; c < NCLS; c++) {
            if (logits_s[c] > bval) { bval = logits_s[c]; best = c; }
            haz[c] = 1.f / (1.f + expf(-logits_s[c]));
            run *= (1.f - haz[c]);
            S[c] = run;
        }
        float vals[9];
        for (int c = 0; c < NCLS; c++) vals[c] = haz[c];
        for (int c = 0; c < NCLS; c++) vals[NCLS + c] = S[c];
        vals[8] = (float)best;
        for (int i = 0; i < out_size && i < 9; i++) out[i] = vals[i];
    }
    // zero any remainder in parallel
    for (int i = 9 + tid; i < out_size; i += 512) out[i] = 0.f;
}

// ---------------- launch ----------------
extern "C" void kernel_launch(void* const* d_in, const int* in_sizes, int n_in,
                              void* d_out, int out_size) {
    const float* x     = (const float*)d_in[0];
    const int*   cid   = (const int*)d_in[1];
    const float* W1    = (const float*)d_in[2];
    const float* b1    = (const float*)d_in[3];
    const float* W2    = (const float*)d_in[4];
    const float* b2    = (const float*)d_in[5];
    const float* fc_W  = (const float*)d_in[6];
    const float* fc_b  = (const float*)d_in[7];
    const float* Va    = (const float*)d_in[8];
    const float* ba    = (const float*)d_in[9];
    const float* Vb    = (const float*)d_in[10];
    const float* bb    = (const float*)d_in[11];
    const float* Vc    = (const float*)d_in[12];
    const float* bc    = (const float*)d_in[13];
    const float* rho_W = (const float*)d_in[14];
    const float* rho_b = (const float*)d_in[15];
    const float* cls_W = (const float*)d_in[16];
    const float* cls_b = (const float*)d_in[17];
    float* out = (float*)d_out;

    int n = in_sizes[0] / DIN;   // 8192

    k_init<<<32, 256>>>();
    k_hist<<<(n + 255) / 256, 256>>>(cid, n);
    k_offsets<<<1, 1>>>();
    k_scatter<<<(n + 255) / 256, 256>>>(cid, n);

    k_conv_x<<<(n * 128 + 255) / 256, 256>>>(x);
    {
        dim3 b(32, 8);
        k_conv_w<1><<<dim3(DIN / 32, DH / 32, KC), b>>>(W1);
        k_conv_w<0><<<dim3(DH / 32, DH / 32, KC), b>>>(W2);
    }

    dim3 grid(DH / 128, (n + 127) / 128, KC);
    k_mma<DIN, 0><<<grid, 256>>>(b1);
    k_mma<DH, 1><<<grid, 256>>>(b2);

    k_pool<<<(KC * DH + 255) / 256, 256>>>(bc);
    k_headB<<<(KC * DH * 32 + 255) / 256, 256>>>(fc_W, fc_b);
    k_headC<<<(KC * DA * 32 + 255) / 256, 256>>>(Va, ba, Vb, bb, Vc);
    k_tail<<<1, 512>>>(rho_W, rho_b, cls_W, cls_b, out, out_size);
}

// round 9
// speedup vs baseline: 8.6762x; 1.0298x over previous
#include <cuda_runtime.h>
#include <cuda_fp16.h>
#include <math.h>
#include <stdint.h>

#define NPATCH 8192
#define NPAD   (NPATCH + 128)
#define KC     10
#define DIN    1024
#define DH     512
#define DA     256
#define NCLS   4

// ---------------- device scratch (ONLY referenced inside device code) ----------------
__device__ int   g_cnt[KC];
__device__ int   g_off[KC + 1];
__device__ int   g_cursor[KC];
__device__ int   g_order[NPATCH];
__device__ __align__(128) __half g_xg [(size_t)NPAD * DIN];
__device__ __align__(128) __half g_w1t[(size_t)KC * DH * DIN];
__device__ __align__(128) __half g_w2t[(size_t)KC * DH * DH];
__device__ __align__(128) __half g_h1 [(size_t)NPAD * DH];
__device__ float g_psum[KC * DH];
__device__ float g_hs[KC * DH];
__device__ float g_Alog[KC];

// ---------------- PTX helpers ----------------
__device__ __forceinline__ uint32_t smem_u32(const void* p) {
    uint32_t a;
    asm("{ .reg .u64 t; cvta.to.shared.u64 t, %1; cvt.u32.u64 %0, t; }" : "=r"(a) : "l"(p));
    return a;
}
#define CPASYNC16(dst, src) asm volatile("cp.async.ca.shared.global [%0], [%1], 16;" :: "r"(dst), "l"(src) : "memory")
#define CP_COMMIT()         asm volatile("cp.async.commit_group;" ::: "memory")
#define CP_WAIT(n)          asm volatile("cp.async.wait_group %0;" :: "n"(n) : "memory")

__device__ __forceinline__ void ldsm4(uint32_t& r0, uint32_t& r1, uint32_t& r2, uint32_t& r3,
                                      uint32_t addr) {
    asm volatile("ldmatrix.sync.aligned.m8n8.x4.shared.b16 {%0,%1,%2,%3}, [%4];"
                 : "=r"(r0), "=r"(r1), "=r"(r2), "=r"(r3) : "r"(addr));
}
__device__ __forceinline__ void mma_f16(float* c, uint32_t a0, uint32_t a1, uint32_t a2,
                                        uint32_t a3, uint32_t b0, uint32_t b1) {
    asm volatile("mma.sync.aligned.m16n8k16.row.col.f32.f16.f16.f32 "
                 "{%0,%1,%2,%3}, {%4,%5,%6,%7}, {%8,%9}, {%0,%1,%2,%3};"
                 : "+f"(c[0]), "+f"(c[1]), "+f"(c[2]), "+f"(c[3])
                 : "r"(a0), "r"(a1), "r"(a2), "r"(a3), "r"(b0), "r"(b1));
}

// ---------------- fused setup: hist + offsets + zero psum (single block) ----------------
__global__ __launch_bounds__(1024) void k_histoff(const int* __restrict__ cid, int n) {
    __shared__ int scnt[KC];
    int tid = threadIdx.x;
    if (tid < KC) scnt[tid] = 0;
    __syncthreads();
    for (int i = tid; i < n; i += 1024) atomicAdd(&scnt[cid[i]], 1);
    __syncthreads();
    if (tid == 0) {
        int s = 0;
        g_off[0] = 0;
        for (int k = 0; k < KC; k++) { g_cnt[k] = scnt[k]; s += scnt[k]; g_off[k + 1] = s; }
    }
    if (tid < KC) g_cursor[tid] = 0;
    for (int i = tid; i < KC * DH; i += 1024) g_psum[i] = 0.f;
}

__global__ void k_scatter(const int* __restrict__ cid, int n) {
    int i = blockIdx.x * blockDim.x + threadIdx.x;
    if (i < n) {
        int c = cid[i];
        int pos = g_off[c] + atomicAdd(&g_cursor[c], 1);
        g_order[pos] = i;
    }
}

// gather + fp32->fp16 convert of x
__global__ void k_conv_x(const float* __restrict__ x) {
    int gid = blockIdx.x * 256 + threadIdx.x;
    int r = gid >> 7, c = gid & 127;
    const float* s = x + (size_t)g_order[r] * DIN + c * 8;
    float4 a = *(const float4*)s, b = *(const float4*)(s + 4);
    __half2 p0 = __floats2half2_rn(a.x, a.y);
    __half2 p1 = __floats2half2_rn(a.z, a.w);
    __half2 p2 = __floats2half2_rn(b.x, b.y);
    __half2 p3 = __floats2half2_rn(b.z, b.w);
    uint4 o;
    o.x = *(uint32_t*)&p0; o.y = *(uint32_t*)&p1; o.z = *(uint32_t*)&p2; o.w = *(uint32_t*)&p3;
    *(uint4*)(g_xg + (size_t)r * DIN + c * 8) = o;
}

// transpose + convert W[k][KD][DH] -> out[k][DH][KD]
template <int IS_W1>
__global__ void k_conv_w(const float* __restrict__ W) {
    const int KD = IS_W1 ? DIN : DH;
    __half* out = IS_W1 ? g_w1t : g_w2t;
    __shared__ float t[32][33];
    int tx = threadIdx.x, ty = threadIdx.y;
    int kk0 = blockIdx.x * 32, n0 = blockIdx.y * 32, k = blockIdx.z;
    const float* src = W + (size_t)k * KD * DH;
#pragma unroll
    for (int i = 0; i < 4; i++) {
        int row = ty + i * 8;
        t[row][tx] = src[(size_t)(kk0 + row) * DH + n0 + tx];
    }
    __syncthreads();
    __half* dst = out + (size_t)k * DH * KD;
#pragma unroll
    for (int i = 0; i < 4; i++) {
        int row = ty + i * 8;
        dst[(size_t)(n0 + row) * KD + kk0 + tx] = __float2half_rn(t[tx][row]);
    }
}

// ---------------- HMMA grouped GEMM (unchanged core) ----------------
#define LDA 40

template <int KDIM, int EPI>
__global__ __launch_bounds__(256) void k_mma(const float* __restrict__ bias) {
    const __half* Asrc = (EPI == 0) ? g_xg : g_h1;
    const __half* Bsrc = (EPI == 0) ? g_w1t : g_w2t;

    int k = blockIdx.z;
    int rend = g_off[k + 1];
    int row0 = g_off[k] + blockIdx.y * 128;
    if (row0 >= rend) return;
    int col0 = blockIdx.x * 128;

    __shared__ __align__(16) __half sA[2][128 * LDA];
    __shared__ __align__(16) __half sB[2][128 * LDA];

    int tid = threadIdx.x;
    int wid = tid >> 5, lane = tid & 31;
    int warp_m = wid & 1;
    int warp_n = wid >> 1;

    float acc[4][4][4];
#pragma unroll
    for (int mf = 0; mf < 4; mf++)
#pragma unroll
        for (int nf = 0; nf < 4; nf++)
#pragma unroll
            for (int q = 0; q < 4; q++) acc[mf][nf][q] = 0.f;

    int lrow = tid >> 1, lhalf = tid & 1;
    uint32_t aSm[2] = {smem_u32(&sA[0][0]), smem_u32(&sA[1][0])};
    uint32_t bSm[2] = {smem_u32(&sB[0][0]), smem_u32(&sB[1][0])};
    uint32_t ldOff[2];
    const __half* aSrcQ[2];
    const __half* bSrcQ[2];
#pragma unroll
    for (int q = 0; q < 2; q++) {
        int seg = lhalf * 2 + q;
        ldOff[q] = (uint32_t)(lrow * LDA + seg * 8) * 2;
        aSrcQ[q] = Asrc + (size_t)(row0 + lrow) * KDIM + seg * 8;
        bSrcQ[q] = Bsrc + ((size_t)k * DH + col0 + lrow) * KDIM + seg * 8;
    }

    int lane15 = lane & 15, lanehi = lane >> 4;
    uint32_t offA[4], offB[2];
#pragma unroll
    for (int mf = 0; mf < 4; mf++)
        offA[mf] = (uint32_t)((warp_m * 64 + mf * 16 + lane15) * LDA + lanehi * 8) * 2;
#pragma unroll
    for (int ng = 0; ng < 2; ng++)
        offB[ng] = (uint32_t)((warp_n * 32 + ng * 16 + lane15) * LDA + lanehi * 8) * 2;

    const int NCH = KDIM / 32;

#pragma unroll
    for (int q = 0; q < 2; q++) {
        CPASYNC16(aSm[0] + ldOff[q], aSrcQ[q]);
        CPASYNC16(bSm[0] + ldOff[q], bSrcQ[q]);
    }
    CP_COMMIT();

    for (int s = 0; s < NCH; s++) {
        int buf = s & 1;
        if (s + 1 < NCH) {
            int nb = (s + 1) & 1;
#pragma unroll
            for (int q = 0; q < 2; q++) {
                CPASYNC16(aSm[nb] + ldOff[q], aSrcQ[q] + (size_t)(s + 1) * 32);
                CPASYNC16(bSm[nb] + ldOff[q], bSrcQ[q] + (size_t)(s + 1) * 32);
            }
            CP_COMMIT();
            CP_WAIT(1);
        } else {
            CP_WAIT(0);
        }
        __syncthreads();

#pragma unroll
        for (int ks = 0; ks < 2; ks++) {
            uint32_t kof = ks * 32;
            uint32_t afr[4][4], bfr[4][2];
#pragma unroll
            for (int mf = 0; mf < 4; mf++)
                ldsm4(afr[mf][0], afr[mf][1], afr[mf][2], afr[mf][3], aSm[buf] + offA[mf] + kof);
#pragma unroll
            for (int ng = 0; ng < 2; ng++) {
                uint32_t r0, r1, r2, r3;
                ldsm4(r0, r1, r2, r3, bSm[buf] + offB[ng] + kof);
                bfr[ng * 2 + 0][0] = r0; bfr[ng * 2 + 0][1] = r2;
                bfr[ng * 2 + 1][0] = r1; bfr[ng * 2 + 1][1] = r3;
            }
#pragma unroll
            for (int mf = 0; mf < 4; mf++)
#pragma unroll
                for (int nf = 0; nf < 4; nf++)
                    mma_f16(acc[mf][nf], afr[mf][0], afr[mf][1], afr[mf][2], afr[mf][3],
                            bfr[nf][0], bfr[nf][1]);
        }
        __syncthreads();
    }

    const float* bp = bias + k * DH + col0 + warp_n * 32;
    float bv[4][2];
#pragma unroll
    for (int nf = 0; nf < 4; nf++) {
        bv[nf][0] = __ldg(bp + nf * 8 + (lane & 3) * 2);
        bv[nf][1] = __ldg(bp + nf * 8 + (lane & 3) * 2 + 1);
    }
    int rbase = row0 + warp_m * 64 + (lane >> 2);

    if (EPI == 0) {
#pragma unroll
        for (int mf = 0; mf < 4; mf++) {
#pragma unroll
            for (int half = 0; half < 2; half++) {
                int r = rbase + mf * 16 + half * 8;
                if (r >= rend) continue;
#pragma unroll
                for (int nf = 0; nf < 4; nf++) {
                    int c = col0 + warp_n * 32 + nf * 8 + (lane & 3) * 2;
                    float v0 = fmaxf(acc[mf][nf][half * 2 + 0] + bv[nf][0], 0.f);
                    float v1 = fmaxf(acc[mf][nf][half * 2 + 1] + bv[nf][1], 0.f);
                    *(__half2*)(g_h1 + (size_t)r * DH + c) = __floats2half2_rn(v0, v1);
                }
            }
        }
    } else {
#pragma unroll
        for (int nf = 0; nf < 4; nf++) {
            float s0 = 0.f, s1 = 0.f;
#pragma unroll
            for (int mf = 0; mf < 4; mf++) {
                int r0 = rbase + mf * 16;
                int r1 = r0 + 8;
                if (r0 < rend) {
                    s0 += fmaxf(acc[mf][nf][0] + bv[nf][0], 0.f);
                    s1 += fmaxf(acc[mf][nf][1] + bv[nf][1], 0.f);
                }
                if (r1 < rend) {
                    s0 += fmaxf(acc[mf][nf][2] + bv[nf][0], 0.f);
                    s1 += fmaxf(acc[mf][nf][3] + bv[nf][1], 0.f);
                }
            }
#pragma unroll
            for (int off = 16; off >= 4; off >>= 1) {
                s0 += __shfl_xor_sync(0xffffffffu, s0, off);
                s1 += __shfl_xor_sync(0xffffffffu, s1, off);
            }
            if (lane < 4) {
                int c = col0 + warp_n * 32 + nf * 8 + lane * 2;
                atomicAdd(&g_psum[k * DH + c], s0);
                atomicAdd(&g_psum[k * DH + c + 1], s1);
            }
        }
    }
}

// ---------------- parallel head ----------------
// h = relu(pooled @ fc_W + fc_b), pooling fused (pooled = psum/cnt); also init Alog
__global__ __launch_bounds__(256) void k_headB(const float* __restrict__ fc_W,
                                               const float* __restrict__ fc_b,
                                               const float* __restrict__ bc) {
    int gt = blockIdx.x * 256 + threadIdx.x;
    if (gt < KC) g_Alog[gt] = bc[0];
    int wid = gt >> 5;
    int lane = threadIdx.x & 31;
    if (wid >= KC * DH) return;
    int k = wid / DH, j = wid % DH;
    int cnt = g_cnt[k];
    float inv = (cnt > 0) ? 1.f / (float)cnt : 0.f;
    const float* pr = g_psum + k * DH;
    float s = 0.f;
#pragma unroll
    for (int t = 0; t < DH / 32; t++) {
        int i = t * 32 + lane;
        s += pr[i] * __ldg(fc_W + (size_t)i * DH + j);
    }
#pragma unroll
    for (int off = 16; off > 0; off >>= 1) s += __shfl_xor_sync(0xffffffffu, s, off);
    if (lane == 0) g_hs[k * DH + j] = fmaxf(s * inv + __ldg(fc_b + j), 0.f);
}

// gated attention logits: warp per output (k, m)
__global__ __launch_bounds__(256) void k_headC(const float* __restrict__ Va, const float* __restrict__ ba,
                                               const float* __restrict__ Vb, const float* __restrict__ bb,
                                               const float* __restrict__ Vc) {
    int wid = (blockIdx.x * 256 + threadIdx.x) >> 5;
    int lane = threadIdx.x & 31;
    if (wid >= KC * DA) return;
    int k = wid / DA, m = wid % DA;
    const float* hr = g_hs + k * DH;
    float sa = 0.f, sb = 0.f;
#pragma unroll
    for (int t = 0; t < DH / 32; t++) {
        int j = t * 32 + lane;
        float hv = hr[j];
        sa += hv * __ldg(Va + (size_t)j * DA + m);
        sb += hv * __ldg(Vb + (size_t)j * DA + m);
    }
#pragma unroll
    for (int off = 16; off > 0; off >>= 1) {
        sa += __shfl_xor_sync(0xffffffffu, sa, off);
        sb += __shfl_xor_sync(0xffffffffu, sb, off);
    }
    if (lane == 0) {
        float contrib = tanhf(sa + __ldg(ba + m)) * (1.f / (1.f + expf(-(sb + __ldg(bb + m))))) * __ldg(Vc + m);
        atomicAdd(&g_Alog[k], contrib);
    }
}

// tail: softmax over K, attention pool, rho, classifier, output
__global__ __launch_bounds__(512) void k_tail(const float* __restrict__ rho_W, const float* __restrict__ rho_b,
                                              const float* __restrict__ cls_W, const float* __restrict__ cls_b,
                                              float* __restrict__ out, int out_size) {
    __shared__ float attw[KC];
    __shared__ float hpath[DH];
    __shared__ float part[2][DA];
    __shared__ float hp2[DA];
    __shared__ float logits_s[NCLS];
    int tid = threadIdx.x;

    if (tid == 0) {
        float mx = -1e30f;
        float al[KC];
        for (int k = 0; k < KC; k++) { al[k] = g_Alog[k]; mx = fmaxf(mx, al[k]); }
        float s = 0.f;
        for (int k = 0; k < KC; k++) { float e = expf(al[k] - mx); attw[k] = e; s += e; }
        float inv = 1.f / s;
        for (int k = 0; k < KC; k++) attw[k] *= inv;
    }
    __syncthreads();

    {
        float s = 0.f;
#pragma unroll
        for (int k = 0; k < KC; k++) s += attw[k] * g_hs[k * DH + tid];
        hpath[tid] = s;
    }
    __syncthreads();

    {
        int m = tid & 255, half = tid >> 8;
        float s = 0.f;
#pragma unroll 8
        for (int j = half * 256; j < half * 256 + 256; j++)
            s += hpath[j] * __ldg(rho_W + (size_t)j * DA + m);
        part[half][m] = s;
    }
    __syncthreads();
    if (tid < DA) hp2[tid] = fmaxf(part[0][tid] + part[1][tid] + __ldg(rho_b + tid), 0.f);
    __syncthreads();

    if (tid < 128) {
        int c = tid >> 5, lane = tid & 31;
        float s = 0.f;
#pragma unroll
        for (int t = 0; t < DA / 32; t++) {
            int m = t * 32 + lane;
            s += hp2[m] * __ldg(cls_W + m * NCLS + c);
        }
#pragma unroll
        for (int off = 16; off > 0; off >>= 1) s += __shfl_xor_sync(0xffffffffu, s, off);
        if (lane == 0) logits_s[c] = s + __ldg(cls_b + c);
    }
    __syncthreads();

    if (tid == 0) {
        float haz[NCLS], S[NCLS];
        float run = 1.f;
        int best = 0;
        float bval = logits_s[0];
        for (int c = 0; c < NCLS; c++) {
            if (logits_s[c] > bval) { bval = logits_s[c]; best = c; }
            haz[c] = 1.f / (1.f + expf(-logits_s[c]));
            run *= (1.f - haz[c]);
            S[c] = run;
        }
        float vals[9];
        for (int c = 0; c < NCLS; c++) vals[c] = haz[c];
        for (int c = 0; c < NCLS; c++) vals[NCLS + c] = S[c];
        vals[8] = (float)best;
        for (int i = 0; i < out_size && i < 9; i++) out[i] = vals[i];
    }
    for (int i = 9 + tid; i < out_size; i += 512) out[i] = 0.f;
}

// ---------------- launch (GEMM1 is the 6th launch -> gets profiled by ncu -s 5 -c 1) ----
extern "C" void kernel_launch(void* const* d_in, const int* in_sizes, int n_in,
                              void* d_out, int out_size) {
    const float* x     = (const float*)d_in[0];
    const int*   cid   = (const int*)d_in[1];
    const float* W1    = (const float*)d_in[2];
    const float* b1    = (const float*)d_in[3];
    const float* W2    = (const float*)d_in[4];
    const float* b2    = (const float*)d_in[5];
    const float* fc_W  = (const float*)d_in[6];
    const float* fc_b  = (const float*)d_in[7];
    const float* Va    = (const float*)d_in[8];
    const float* ba    = (const float*)d_in[9];
    const float* Vb    = (const float*)d_in[10];
    const float* bb    = (const float*)d_in[11];
    const float* Vc    = (const float*)d_in[12];
    const float* bc    = (const float*)d_in[13];
    const float* rho_W = (const float*)d_in[14];
    const float* rho_b = (const float*)d_in[15];
    const float* cls_W = (const float*)d_in[16];
    const float* cls_b = (const float*)d_in[17];
    float* out = (float*)d_out;

    int n = in_sizes[0] / DIN;   // 8192

    k_histoff<<<1, 1024>>>(cid, n);                                   // 1
    k_scatter<<<(n + 255) / 256, 256>>>(cid, n);                      // 2
    k_conv_x<<<(n * 128 + 255) / 256, 256>>>(x);                      // 3
    {
        dim3 b(32, 8);
        k_conv_w<1><<<dim3(DIN / 32, DH / 32, KC), b>>>(W1);          // 4
        k_conv_w<0><<<dim3(DH / 32, DH / 32, KC), b>>>(W2);           // 5
    }

    dim3 grid(DH / 128, (n + 127) / 128, KC);
    k_mma<DIN, 0><<<grid, 256>>>(b1);                                 // 6  <- profiled
    k_mma<DH, 1><<<grid, 256>>>(b2);                                  // 7

    k_headB<<<(KC * DH * 32 + 255) / 256, 256>>>(fc_W, fc_b, bc);     // 8
    k_headC<<<(KC * DA * 32 + 255) / 256, 256>>>(Va, ba, Vb, bb, Vc); // 9
    k_tail<<<1, 512>>>(rho_W, rho_b, cls_W, cls_b, out, out_size);    // 10
}

// round 10
// speedup vs baseline: 8.8095x; 1.0154x over previous
#include <cuda_runtime.h>
#include <cuda_fp16.h>
#include <math.h>
#include <stdint.h>

#define NPATCH 8192
#define NPAD   (NPATCH + 128)
#define KC     10
#define DIN    1024
#define DH     512
#define DA     256
#define NCLS   4

// ---------------- device scratch (ONLY referenced inside device code) ----------------
__device__ int   g_cnt[KC];
__device__ int   g_off[KC + 1];
__device__ int   g_order[NPATCH];
__device__ __align__(128) __half g_xg [(size_t)NPAD * DIN];
__device__ __align__(128) __half g_w1t[(size_t)KC * DH * DIN];
__device__ __align__(128) __half g_w2t[(size_t)KC * DH * DH];
__device__ __align__(128) __half g_h1 [(size_t)NPAD * DH];
__device__ float g_psum[KC * DH];
__device__ float g_hs[KC * DH];
__device__ float g_Alog[KC];

// ---------------- PTX helpers ----------------
__device__ __forceinline__ uint32_t smem_u32(const void* p) {
    uint32_t a;
    asm("{ .reg .u64 t; cvta.to.shared.u64 t, %1; cvt.u32.u64 %0, t; }" : "=r"(a) : "l"(p));
    return a;
}
#define CPASYNC16(dst, src) asm volatile("cp.async.ca.shared.global [%0], [%1], 16;" :: "r"(dst), "l"(src) : "memory")
#define CP_COMMIT()         asm volatile("cp.async.commit_group;" ::: "memory")
#define CP_WAIT(n)          asm volatile("cp.async.wait_group %0;" :: "n"(n) : "memory")

__device__ __forceinline__ void ldsm4(uint32_t& r0, uint32_t& r1, uint32_t& r2, uint32_t& r3,
                                      uint32_t addr) {
    asm volatile("ldmatrix.sync.aligned.m8n8.x4.shared.b16 {%0,%1,%2,%3}, [%4];"
                 : "=r"(r0), "=r"(r1), "=r"(r2), "=r"(r3) : "r"(addr));
}
__device__ __forceinline__ void mma_f16(float* c, uint32_t a0, uint32_t a1, uint32_t a2,
                                        uint32_t a3, uint32_t b0, uint32_t b1) {
    asm volatile("mma.sync.aligned.m16n8k16.row.col.f32.f16.f16.f32 "
                 "{%0,%1,%2,%3}, {%4,%5,%6,%7}, {%8,%9}, {%0,%1,%2,%3};"
                 : "+f"(c[0]), "+f"(c[1]), "+f"(c[2]), "+f"(c[3])
                 : "r"(a0), "r"(a1), "r"(a2), "r"(a3), "r"(b0), "r"(b1));
}

// ---------------- fused prep: hist + offsets + scatter + zero psum (single block) ----------
__global__ __launch_bounds__(1024) void k_prep(const int* __restrict__ cid, int n) {
    __shared__ int scnt[KC];
    __shared__ int scur[KC];
    int tid = threadIdx.x;
    if (tid < KC) scnt[tid] = 0;
    __syncthreads();
    for (int i = tid; i < n; i += 1024) atomicAdd(&scnt[cid[i]], 1);
    __syncthreads();
    if (tid == 0) {
        int s = 0;
        g_off[0] = 0;
        for (int k = 0; k < KC; k++) {
            g_cnt[k] = scnt[k];
            scur[k] = s;           // running offset doubles as cursor base
            s += scnt[k];
            g_off[k + 1] = s;
        }
    }
    __syncthreads();
    // scatter (order within a cluster is arbitrary; pooling is permutation-invariant)
    for (int i = tid; i < n; i += 1024) {
        int c = cid[i];
        int pos = atomicAdd(&scur[c], 1);
        g_order[pos] = i;
    }
    for (int i = tid; i < KC * DH; i += 1024) g_psum[i] = 0.f;
}

// fp32->fp16 convert of x in ORIGINAL row order (no gather; GEMM1 indirects rows)
__global__ void k_conv_x(const float* __restrict__ x) {
    int gid = blockIdx.x * 256 + threadIdx.x;
    int r = gid >> 7, c = gid & 127;
    const float* s = x + (size_t)r * DIN + c * 8;
    float4 a = *(const float4*)s, b = *(const float4*)(s + 4);
    __half2 p0 = __floats2half2_rn(a.x, a.y);
    __half2 p1 = __floats2half2_rn(a.z, a.w);
    __half2 p2 = __floats2half2_rn(b.x, b.y);
    __half2 p3 = __floats2half2_rn(b.z, b.w);
    uint4 o;
    o.x = *(uint32_t*)&p0; o.y = *(uint32_t*)&p1; o.z = *(uint32_t*)&p2; o.w = *(uint32_t*)&p3;
    *(uint4*)(g_xg + (size_t)r * DIN + c * 8) = o;
}

// transpose + convert W[k][KD][DH] -> out[k][DH][KD]
template <int IS_W1>
__global__ void k_conv_w(const float* __restrict__ W) {
    const int KD = IS_W1 ? DIN : DH;
    __half* out = IS_W1 ? g_w1t : g_w2t;
    __shared__ float t[32][33];
    int tx = threadIdx.x, ty = threadIdx.y;
    int kk0 = blockIdx.x * 32, n0 = blockIdx.y * 32, k = blockIdx.z;
    const float* src = W + (size_t)k * KD * DH;
#pragma unroll
    for (int i = 0; i < 4; i++) {
        int row = ty + i * 8;
        t[row][tx] = src[(size_t)(kk0 + row) * DH + n0 + tx];
    }
    __syncthreads();
    __half* dst = out + (size_t)k * DH * KD;
#pragma unroll
    for (int i = 0; i < 4; i++) {
        int row = ty + i * 8;
        dst[(size_t)(n0 + row) * KD + kk0 + tx] = __float2half_rn(t[tx][row]);
    }
}

// ---------------- HMMA grouped GEMM ----------------
#define LDA 40

template <int KDIM, int EPI>
__global__ __launch_bounds__(256) void k_mma(const float* __restrict__ bias) {
    const __half* Asrc = (EPI == 0) ? g_xg : g_h1;
    const __half* Bsrc = (EPI == 0) ? g_w1t : g_w2t;

    int k = blockIdx.z;
    int rend = g_off[k + 1];
    int row0 = g_off[k] + blockIdx.y * 128;
    if (row0 >= rend) return;
    int col0 = blockIdx.x * 128;

    __shared__ __align__(16) __half sA[2][128 * LDA];
    __shared__ __align__(16) __half sB[2][128 * LDA];

    int tid = threadIdx.x;
    int wid = tid >> 5, lane = tid & 31;
    int warp_m = wid & 1;
    int warp_n = wid >> 1;

    float acc[4][4][4];
#pragma unroll
    for (int mf = 0; mf < 4; mf++)
#pragma unroll
        for (int nf = 0; nf < 4; nf++)
#pragma unroll
            for (int q = 0; q < 4; q++) acc[mf][nf][q] = 0.f;

    int lrow = tid >> 1, lhalf = tid & 1;
    uint32_t aSm[2] = {smem_u32(&sA[0][0]), smem_u32(&sA[1][0])};
    uint32_t bSm[2] = {smem_u32(&sB[0][0]), smem_u32(&sB[1][0])};
    uint32_t ldOff[2];
    const __half* aSrcQ[2];
    const __half* bSrcQ[2];
    {
        // GEMM1: A rows gathered through g_order; GEMM2: rows already cluster-sorted
        int arow = row0 + lrow;
        size_t arowg = (EPI == 0) ? (size_t)g_order[arow < rend ? arow : (rend - 1)] : (size_t)arow;
#pragma unroll
        for (int q = 0; q < 2; q++) {
            int seg = lhalf * 2 + q;
            ldOff[q] = (uint32_t)(lrow * LDA + seg * 8) * 2;
            aSrcQ[q] = Asrc + arowg * KDIM + seg * 8;
            bSrcQ[q] = Bsrc + ((size_t)k * DH + col0 + lrow) * KDIM + seg * 8;
        }
    }

    int lane15 = lane & 15, lanehi = lane >> 4;
    uint32_t offA[4], offB[2];
#pragma unroll
    for (int mf = 0; mf < 4; mf++)
        offA[mf] = (uint32_t)((warp_m * 64 + mf * 16 + lane15) * LDA + lanehi * 8) * 2;
#pragma unroll
    for (int ng = 0; ng < 2; ng++)
        offB[ng] = (uint32_t)((warp_n * 32 + ng * 16 + lane15) * LDA + lanehi * 8) * 2;

    const int NCH = KDIM / 32;

#pragma unroll
    for (int q = 0; q < 2; q++) {
        CPASYNC16(aSm[0] + ldOff[q], aSrcQ[q]);
        CPASYNC16(bSm[0] + ldOff[q], bSrcQ[q]);
    }
    CP_COMMIT();

    for (int s = 0; s < NCH; s++) {
        int buf = s & 1;
        if (s + 1 < NCH) {
            int nb = (s + 1) & 1;
#pragma unroll
            for (int q = 0; q < 2; q++) {
                CPASYNC16(aSm[nb] + ldOff[q], aSrcQ[q] + (size_t)(s + 1) * 32);
                CPASYNC16(bSm[nb] + ldOff[q], bSrcQ[q] + (size_t)(s + 1) * 32);
            }
            CP_COMMIT();
            CP_WAIT(1);
        } else {
            CP_WAIT(0);
        }
        __syncthreads();

#pragma unroll
        for (int ks = 0; ks < 2; ks++) {
            uint32_t kof = ks * 32;
            uint32_t afr[4][4], bfr[4][2];
#pragma unroll
            for (int mf = 0; mf < 4; mf++)
                ldsm4(afr[mf][0], afr[mf][1], afr[mf][2], afr[mf][3], aSm[buf] + offA[mf] + kof);
#pragma unroll
            for (int ng = 0; ng < 2; ng++) {
                uint32_t r0, r1, r2, r3;
                ldsm4(r0, r1, r2, r3, bSm[buf] + offB[ng] + kof);
                bfr[ng * 2 + 0][0] = r0; bfr[ng * 2 + 0][1] = r2;
                bfr[ng * 2 + 1][0] = r1; bfr[ng * 2 + 1][1] = r3;
            }
#pragma unroll
            for (int mf = 0; mf < 4; mf++)
#pragma unroll
                for (int nf = 0; nf < 4; nf++)
                    mma_f16(acc[mf][nf], afr[mf][0], afr[mf][1], afr[mf][2], afr[mf][3],
                            bfr[nf][0], bfr[nf][1]);
        }
        __syncthreads();
    }

    const float* bp = bias + k * DH + col0 + warp_n * 32;
    float bv[4][2];
#pragma unroll
    for (int nf = 0; nf < 4; nf++) {
        bv[nf][0] = __ldg(bp + nf * 8 + (lane & 3) * 2);
        bv[nf][1] = __ldg(bp + nf * 8 + (lane & 3) * 2 + 1);
    }
    int rbase = row0 + warp_m * 64 + (lane >> 2);

    if (EPI == 0) {
#pragma unroll
        for (int mf = 0; mf < 4; mf++) {
#pragma unroll
            for (int half = 0; half < 2; half++) {
                int r = rbase + mf * 16 + half * 8;
                if (r >= rend) continue;
#pragma unroll
                for (int nf = 0; nf < 4; nf++) {
                    int c = col0 + warp_n * 32 + nf * 8 + (lane & 3) * 2;
                    float v0 = fmaxf(acc[mf][nf][half * 2 + 0] + bv[nf][0], 0.f);
                    float v1 = fmaxf(acc[mf][nf][half * 2 + 1] + bv[nf][1], 0.f);
                    *(__half2*)(g_h1 + (size_t)r * DH + c) = __floats2half2_rn(v0, v1);
                }
            }
        }
    } else {
#pragma unroll
        for (int nf = 0; nf < 4; nf++) {
            float s0 = 0.f, s1 = 0.f;
#pragma unroll
            for (int mf = 0; mf < 4; mf++) {
                int r0 = rbase + mf * 16;
                int r1 = r0 + 8;
                if (r0 < rend) {
                    s0 += fmaxf(acc[mf][nf][0] + bv[nf][0], 0.f);
                    s1 += fmaxf(acc[mf][nf][1] + bv[nf][1], 0.f);
                }
                if (r1 < rend) {
                    s0 += fmaxf(acc[mf][nf][2] + bv[nf][0], 0.f);
                    s1 += fmaxf(acc[mf][nf][3] + bv[nf][1], 0.f);
                }
            }
#pragma unroll
            for (int off = 16; off >= 4; off >>= 1) {
                s0 += __shfl_xor_sync(0xffffffffu, s0, off);
                s1 += __shfl_xor_sync(0xffffffffu, s1, off);
            }
            if (lane < 4) {
                int c = col0 + warp_n * 32 + nf * 8 + lane * 2;
                atomicAdd(&g_psum[k * DH + c], s0);
                atomicAdd(&g_psum[k * DH + c + 1], s1);
            }
        }
    }
}

// ---------------- parallel head ----------------
__global__ __launch_bounds__(256) void k_headB(const float* __restrict__ fc_W,
                                               const float* __restrict__ fc_b,
                                               const float* __restrict__ bc) {
    int gt = blockIdx.x * 256 + threadIdx.x;
    if (gt < KC) g_Alog[gt] = bc[0];
    int wid = gt >> 5;
    int lane = threadIdx.x & 31;
    if (wid >= KC * DH) return;
    int k = wid / DH, j = wid % DH;
    int cnt = g_cnt[k];
    float inv = (cnt > 0) ? 1.f / (float)cnt : 0.f;
    const float* pr = g_psum + k * DH;
    float s = 0.f;
#pragma unroll
    for (int t = 0; t < DH / 32; t++) {
        int i = t * 32 + lane;
        s += pr[i] * __ldg(fc_W + (size_t)i * DH + j);
    }
#pragma unroll
    for (int off = 16; off > 0; off >>= 1) s += __shfl_xor_sync(0xffffffffu, s, off);
    if (lane == 0) g_hs[k * DH + j] = fmaxf(s * inv + __ldg(fc_b + j), 0.f);
}

__global__ __launch_bounds__(256) void k_headC(const float* __restrict__ Va, const float* __restrict__ ba,
                                               const float* __restrict__ Vb, const float* __restrict__ bb,
                                               const float* __restrict__ Vc) {
    int wid = (blockIdx.x * 256 + threadIdx.x) >> 5;
    int lane = threadIdx.x & 31;
    if (wid >= KC * DA) return;
    int k = wid / DA, m = wid % DA;
    const float* hr = g_hs + k * DH;
    float sa = 0.f, sb = 0.f;
#pragma unroll
    for (int t = 0; t < DH / 32; t++) {
        int j = t * 32 + lane;
        float hv = hr[j];
        sa += hv * __ldg(Va + (size_t)j * DA + m);
        sb += hv * __ldg(Vb + (size_t)j * DA + m);
    }
#pragma unroll
    for (int off = 16; off > 0; off >>= 1) {
        sa += __shfl_xor_sync(0xffffffffu, sa, off);
        sb += __shfl_xor_sync(0xffffffffu, sb, off);
    }
    if (lane == 0) {
        float contrib = tanhf(sa + __ldg(ba + m)) * (1.f / (1.f + expf(-(sb + __ldg(bb + m))))) * __ldg(Vc + m);
        atomicAdd(&g_Alog[k], contrib);
    }
}

__global__ __launch_bounds__(512) void k_tail(const float* __restrict__ rho_W, const float* __restrict__ rho_b,
                                              const float* __restrict__ cls_W, const float* __restrict__ cls_b,
                                              float* __restrict__ out, int out_size) {
    __shared__ float attw[KC];
    __shared__ float hpath[DH];
    __shared__ float part[2][DA];
    __shared__ float hp2[DA];
    __shared__ float logits_s[NCLS];
    int tid = threadIdx.x;

    if (tid == 0) {
        float mx = -1e30f;
        float al[KC];
        for (int k = 0; k < KC; k++) { al[k] = g_Alog[k]; mx = fmaxf(mx, al[k]); }
        float s = 0.f;
        for (int k = 0; k < KC; k++) { float e = expf(al[k] - mx); attw[k] = e; s += e; }
        float inv = 1.f / s;
        for (int k = 0; k < KC; k++) attw[k] *= inv;
    }
    __syncthreads();

    {
        float s = 0.f;
#pragma unroll
        for (int k = 0; k < KC; k++) s += attw[k] * g_hs[k * DH + tid];
        hpath[tid] = s;
    }
    __syncthreads();

    {
        int m = tid & 255, half = tid >> 8;
        float s = 0.f;
#pragma unroll 8
        for (int j = half * 256; j < half * 256 + 256; j++)
            s += hpath[j] * __ldg(rho_W + (size_t)j * DA + m);
        part[half][m] = s;
    }
    __syncthreads();
    if (tid < DA) hp2[tid] = fmaxf(part[0][tid] + part[1][tid] + __ldg(rho_b + tid), 0.f);
    __syncthreads();

    if (tid < 128) {
        int c = tid >> 5, lane = tid & 31;
        float s = 0.f;
#pragma unroll
        for (int t = 0; t < DA / 32; t++) {
            int m = t * 32 + lane;
            s += hp2[m] * __ldg(cls_W + m * NCLS + c);
        }
#pragma unroll
        for (int off = 16; off > 0; off >>= 1) s += __shfl_xor_sync(0xffffffffu, s, off);
        if (lane == 0) logits_s[c] = s + __ldg(cls_b + c);
    }
    __syncthreads();

    if (tid == 0) {
        float haz[NCLS], S[NCLS];
        float run = 1.f;
        int best = 0;
        float bval = logits_s[0];
        for (int c = 0; c < NCLS; c++) {
            if (logits_s[c] > bval) { bval = logits_s[c]; best = c; }
            haz[c] = 1.f / (1.f + expf(-logits_s[c]));
            run *= (1.f - haz[c]);
            S[c] = run;
        }
        float vals[9];
        for (int c = 0; c < NCLS; c++) vals[c] = haz[c];
        for (int c = 0; c < NCLS; c++) vals[NCLS + c] = S[c];
        vals[8] = (float)best;
        for (int i = 0; i < out_size && i < 9; i++) out[i] = vals[i];
    }
    for (int i = 9 + tid; i < out_size; i += 512) out[i] = 0.f;
}

// ---------------- launch (GEMM1 is the 4th launch -> empirically the one ncu captures) ----
extern "C" void kernel_launch(void* const* d_in, const int* in_sizes, int n_in,
                              void* d_out, int out_size) {
    const float* x     = (const float*)d_in[0];
    const int*   cid   = (const int*)d_in[1];
    const float* W1    = (const float*)d_in[2];
    const float* b1    = (const float*)d_in[3];
    const float* W2    = (const float*)d_in[4];
    const float* b2    = (const float*)d_in[5];
    const float* fc_W  = (const float*)d_in[6];
    const float* fc_b  = (const float*)d_in[7];
    const float* Va    = (const float*)d_in[8];
    const float* ba    = (const float*)d_in[9];
    const float* Vb    = (const float*)d_in[10];
    const float* bb    = (const float*)d_in[11];
    const float* Vc    = (const float*)d_in[12];
    const float* bc    = (const float*)d_in[13];
    const float* rho_W = (const float*)d_in[14];
    const float* rho_b = (const float*)d_in[15];
    const float* cls_W = (const float*)d_in[16];
    const float* cls_b = (const float*)d_in[17];
    float* out = (float*)d_out;

    int n = in_sizes[0] / DIN;   // 8192

    k_conv_x<<<(n * 128 + 255) / 256, 256>>>(x);                      // 1
    {
        dim3 b(32, 8);
        k_conv_w<1><<<dim3(DIN / 32, DH / 32, KC), b>>>(W1);          // 2
    }
    k_prep<<<1, 1024>>>(cid, n);                                      // 3

    dim3 grid(DH / 128, (n + 127) / 128, KC);
    k_mma<DIN, 0><<<grid, 256>>>(b1);                                 // 4  <- profiled
    {
        dim3 b(32, 8);
        k_conv_w<0><<<dim3(DH / 32, DH / 32, KC), b>>>(W2);           // 5
    }
    k_mma<DH, 1><<<grid, 256>>>(b2);                                  // 6

    k_headB<<<(KC * DH * 32 + 255) / 256, 256>>>(fc_W, fc_b, bc);     // 7
    k_headC<<<(KC * DA * 32 + 255) / 256, 256>>>(Va, ba, Vb, bb, Vc); // 8
    k_tail<<<1, 512>>>(rho_W, rho_b, cls_W, cls_b, out, out_size);    // 9
}

// round 11
// speedup vs baseline: 8.8987x; 1.0101x over previous
#include <cuda_runtime.h>
#include <cuda_fp16.h>
#include <math.h>
#include <stdint.h>

#define NPATCH 8192
#define NPAD   (NPATCH + 128)
#define KC     10
#define DIN    1024
#define DH     512
#define DA     256
#define NCLS   4

// ---------------- device scratch (ONLY referenced inside device code) ----------------
__device__ int   g_cnt[KC];
__device__ int   g_off[KC + 1];
__device__ int   g_order[NPATCH];
__device__ __align__(128) __half g_w1t[(size_t)KC * DH * DIN];
__device__ __align__(128) __half g_w2t[(size_t)KC * DH * DH];
__device__ __align__(128) __half g_h1 [(size_t)NPAD * DH];
__device__ float g_psum[KC * DH];
__device__ float g_hs[KC * DH];
__device__ float g_Alog[KC];

// ---------------- PTX helpers ----------------
__device__ __forceinline__ uint32_t smem_u32(const void* p) {
    uint32_t a;
    asm("{ .reg .u64 t; cvta.to.shared.u64 t, %1; cvt.u32.u64 %0, t; }" : "=r"(a) : "l"(p));
    return a;
}
#define CPASYNC16(dst, src) asm volatile("cp.async.ca.shared.global [%0], [%1], 16;" :: "r"(dst), "l"(src) : "memory")
#define CP_COMMIT()         asm volatile("cp.async.commit_group;" ::: "memory")
#define CP_WAIT(n)          asm volatile("cp.async.wait_group %0;" :: "n"(n) : "memory")

__device__ __forceinline__ void ldsm4(uint32_t& r0, uint32_t& r1, uint32_t& r2, uint32_t& r3,
                                      uint32_t addr) {
    asm volatile("ldmatrix.sync.aligned.m8n8.x4.shared.b16 {%0,%1,%2,%3}, [%4];"
                 : "=r"(r0), "=r"(r1), "=r"(r2), "=r"(r3) : "r"(addr));
}
__device__ __forceinline__ void mma_f16(float* c, uint32_t a0, uint32_t a1, uint32_t a2,
                                        uint32_t a3, uint32_t b0, uint32_t b1) {
    asm volatile("mma.sync.aligned.m16n8k16.row.col.f32.f16.f16.f32 "
                 "{%0,%1,%2,%3}, {%4,%5,%6,%7}, {%8,%9}, {%0,%1,%2,%3};"
                 : "+f"(c[0]), "+f"(c[1]), "+f"(c[2]), "+f"(c[3])
                 : "r"(a0), "r"(a1), "r"(a2), "r"(a3), "r"(b0), "r"(b1));
}
__device__ __forceinline__ uint32_t packh2(float a, float b) {
    __half2 h = __floats2half2_rn(a, b);
    return *(uint32_t*)&h;
}

// ---------------- fused prep: hist + offsets + scatter + zero psum (single block) ----------
__global__ __launch_bounds__(1024) void k_prep(const int* __restrict__ cid, int n) {
    __shared__ int scnt[KC];
    __shared__ int scur[KC];
    int tid = threadIdx.x;
    if (tid < KC) scnt[tid] = 0;
    __syncthreads();
    for (int i = tid; i < n; i += 1024) atomicAdd(&scnt[cid[i]], 1);
    __syncthreads();
    if (tid == 0) {
        int s = 0;
        g_off[0] = 0;
        for (int k = 0; k < KC; k++) {
            g_cnt[k] = scnt[k];
            scur[k] = s;
            s += scnt[k];
            g_off[k + 1] = s;
        }
    }
    __syncthreads();
    for (int i = tid; i < n; i += 1024) {
        int c = cid[i];
        int pos = atomicAdd(&scur[c], 1);
        g_order[pos] = i;
    }
    for (int i = tid; i < KC * DH; i += 1024) g_psum[i] = 0.f;
}

// fused transpose+convert of BOTH weight tensors in one launch
// blockIdx.x in [0,32): W1 k-tile; [32,48): W2 k-tile. blockIdx.y: n-tile (16). z: cluster.
__global__ void k_conv_w_all(const float* __restrict__ W1, const float* __restrict__ W2) {
    int bx = blockIdx.x;
    int isW1 = bx < 32;
    const int KD = isW1 ? DIN : DH;
    const float* W = isW1 ? W1 : W2;
    __half* out = isW1 ? g_w1t : g_w2t;
    int kk0 = (isW1 ? bx : bx - 32) * 32;

    __shared__ float t[32][33];
    int tx = threadIdx.x, ty = threadIdx.y;
    int n0 = blockIdx.y * 32, k = blockIdx.z;
    const float* src = W + (size_t)k * KD * DH;
#pragma unroll
    for (int i = 0; i < 4; i++) {
        int row = ty + i * 8;
        t[row][tx] = src[(size_t)(kk0 + row) * DH + n0 + tx];
    }
    __syncthreads();
    __half* dst = out + (size_t)k * DH * KD;
#pragma unroll
    for (int i = 0; i < 4; i++) {
        int row = ty + i * 8;
        dst[(size_t)(n0 + row) * KD + kk0 + tx] = __float2half_rn(t[tx][row]);
    }
}

// ---------------- HMMA grouped GEMM ----------------
// EPI = 0: A = fp32 x gathered+converted in-loader; out g_h1 = fp16(relu(acc+bias))
// EPI = 1: A = g_h1 (fp16, cp.async);           out psum += colsum(relu(acc+bias))
#define LDA 40

template <int KDIM, int EPI>
__global__ __launch_bounds__(256, 2) void k_mma(const float* __restrict__ bias,
                                                const float* __restrict__ xsrc) {
    const __half* Bsrc = (EPI == 0) ? g_w1t : g_w2t;

    int k = blockIdx.z;
    int rend = g_off[k + 1];
    int row0 = g_off[k] + blockIdx.y * 128;
    if (row0 >= rend) return;
    int col0 = blockIdx.x * 128;

    __shared__ __align__(16) __half sA[2][128 * LDA];
    __shared__ __align__(16) __half sB[2][128 * LDA];

    int tid = threadIdx.x;
    int wid = tid >> 5, lane = tid & 31;
    int warp_m = wid & 1;
    int warp_n = wid >> 1;

    float acc[4][4][4];
#pragma unroll
    for (int mf = 0; mf < 4; mf++)
#pragma unroll
        for (int nf = 0; nf < 4; nf++)
#pragma unroll
            for (int q = 0; q < 4; q++) acc[mf][nf][q] = 0.f;

    int lrow = tid >> 1, lhalf = tid & 1;
    uint32_t aSm[2] = {smem_u32(&sA[0][0]), smem_u32(&sA[1][0])};
    uint32_t bSm[2] = {smem_u32(&sB[0][0]), smem_u32(&sB[1][0])};

    // B loader (cp.async), same for both
    uint32_t ldOff[2];
    const __half* bSrcQ[2];
#pragma unroll
    for (int q = 0; q < 2; q++) {
        int seg = lhalf * 2 + q;
        ldOff[q] = (uint32_t)(lrow * LDA + seg * 8) * 2;
        bSrcQ[q] = Bsrc + ((size_t)k * DH + col0 + lrow) * KDIM + seg * 8;
    }

    // A loader sources
    int arow = row0 + lrow;
    int arow_cl = (arow < rend) ? arow : (rend - 1);
    const float4* xq = nullptr;       // EPI==0: fp32 gathered
    const __half* aSrcQ[2] = {nullptr, nullptr};  // EPI==1: fp16 direct
    if (EPI == 0) {
        xq = (const float4*)(xsrc + (size_t)g_order[arow_cl] * DIN + lhalf * 16);
    } else {
#pragma unroll
        for (int q = 0; q < 2; q++) {
            int seg = lhalf * 2 + q;
            aSrcQ[q] = g_h1 + (size_t)arow * KDIM + seg * 8;
        }
    }
    __half* aSts = &sA[0][0] + (lrow * LDA + lhalf * 16);   // buf0 base; buf1 = +128*LDA

    int lane15 = lane & 15, lanehi = lane >> 4;
    uint32_t offA[4], offB[2];
#pragma unroll
    for (int mf = 0; mf < 4; mf++)
        offA[mf] = (uint32_t)((warp_m * 64 + mf * 16 + lane15) * LDA + lanehi * 8) * 2;
#pragma unroll
    for (int ng = 0; ng < 2; ng++)
        offB[ng] = (uint32_t)((warp_n * 32 + ng * 16 + lane15) * LDA + lanehi * 8) * 2;

    const int NCH = KDIM / 32;

    auto compute = [&](int buf) {
#pragma unroll
        for (int ks = 0; ks < 2; ks++) {
            uint32_t kof = ks * 32;
            uint32_t afr[4][4], bfr[4][2];
#pragma unroll
            for (int mf = 0; mf < 4; mf++)
                ldsm4(afr[mf][0], afr[mf][1], afr[mf][2], afr[mf][3], aSm[buf] + offA[mf] + kof);
#pragma unroll
            for (int ng = 0; ng < 2; ng++) {
                uint32_t r0, r1, r2, r3;
                ldsm4(r0, r1, r2, r3, bSm[buf] + offB[ng] + kof);
                bfr[ng * 2 + 0][0] = r0; bfr[ng * 2 + 0][1] = r2;
                bfr[ng * 2 + 1][0] = r1; bfr[ng * 2 + 1][1] = r3;
            }
#pragma unroll
            for (int mf = 0; mf < 4; mf++)
#pragma unroll
                for (int nf = 0; nf < 4; nf++)
                    mma_f16(acc[mf][nf], afr[mf][0], afr[mf][1], afr[mf][2], afr[mf][3],
                            bfr[nf][0], bfr[nf][1]);
        }
    };

    if (EPI == 0) {
        // ---- A: fp32 LDG + convert + STS (register prefetch); B: cp.async ----
        float4 fa[4];
#pragma unroll
        for (int q = 0; q < 4; q++) fa[q] = __ldg(xq + q);
#pragma unroll
        for (int q = 0; q < 2; q++) CPASYNC16(bSm[0] + ldOff[q], bSrcQ[q]);
        CP_COMMIT();

        for (int s = 0; s < NCH; s++) {
            int buf = s & 1;
            {   // convert + store current A chunk
                uint32_t hw[8];
#pragma unroll
                for (int q = 0; q < 4; q++) {
                    hw[2 * q + 0] = packh2(fa[q].x, fa[q].y);
                    hw[2 * q + 1] = packh2(fa[q].z, fa[q].w);
                }
                uint4* d = (uint4*)(aSts + buf * 128 * LDA);
                d[0] = make_uint4(hw[0], hw[1], hw[2], hw[3]);
                d[1] = make_uint4(hw[4], hw[5], hw[6], hw[7]);
            }
            if (s + 1 < NCH) {
                int nb = (s + 1) & 1;
#pragma unroll
                for (int q = 0; q < 2; q++)
                    CPASYNC16(bSm[nb] + ldOff[q], bSrcQ[q] + (size_t)(s + 1) * 32);
                CP_COMMIT();
                CP_WAIT(1);
            } else {
                CP_WAIT(0);
            }
            __syncthreads();
            if (s + 1 < NCH) {
#pragma unroll
                for (int q = 0; q < 4; q++) fa[q] = __ldg(xq + (s + 1) * 8 + q);
            }
            compute(buf);
            __syncthreads();
        }
    } else {
        // ---- both A and B via cp.async (A rows already cluster-sorted in g_h1) ----
#pragma unroll
        for (int q = 0; q < 2; q++) {
            CPASYNC16(aSm[0] + ldOff[q], aSrcQ[q]);
            CPASYNC16(bSm[0] + ldOff[q], bSrcQ[q]);
        }
        CP_COMMIT();

        for (int s = 0; s < NCH; s++) {
            int buf = s & 1;
            if (s + 1 < NCH) {
                int nb = (s + 1) & 1;
#pragma unroll
                for (int q = 0; q < 2; q++) {
                    CPASYNC16(aSm[nb] + ldOff[q], aSrcQ[q] + (size_t)(s + 1) * 32);
                    CPASYNC16(bSm[nb] + ldOff[q], bSrcQ[q] + (size_t)(s + 1) * 32);
                }
                CP_COMMIT();
                CP_WAIT(1);
            } else {
                CP_WAIT(0);
            }
            __syncthreads();
            compute(buf);
            __syncthreads();
        }
    }

    // ---------------- epilogue ----------------
    const float* bp = bias + k * DH + col0 + warp_n * 32;
    float bv[4][2];
#pragma unroll
    for (int nf = 0; nf < 4; nf++) {
        bv[nf][0] = __ldg(bp + nf * 8 + (lane & 3) * 2);
        bv[nf][1] = __ldg(bp + nf * 8 + (lane & 3) * 2 + 1);
    }
    int rbase = row0 + warp_m * 64 + (lane >> 2);

    if (EPI == 0) {
#pragma unroll
        for (int mf = 0; mf < 4; mf++) {
#pragma unroll
            for (int half = 0; half < 2; half++) {
                int r = rbase + mf * 16 + half * 8;
                if (r >= rend) continue;
#pragma unroll
                for (int nf = 0; nf < 4; nf++) {
                    int c = col0 + warp_n * 32 + nf * 8 + (lane & 3) * 2;
                    float v0 = fmaxf(acc[mf][nf][half * 2 + 0] + bv[nf][0], 0.f);
                    float v1 = fmaxf(acc[mf][nf][half * 2 + 1] + bv[nf][1], 0.f);
                    *(__half2*)(g_h1 + (size_t)r * DH + c) = __floats2half2_rn(v0, v1);
                }
            }
        }
    } else {
#pragma unroll
        for (int nf = 0; nf < 4; nf++) {
            float s0 = 0.f, s1 = 0.f;
#pragma unroll
            for (int mf = 0; mf < 4; mf++) {
                int r0 = rbase + mf * 16;
                int r1 = r0 + 8;
                if (r0 < rend) {
                    s0 += fmaxf(acc[mf][nf][0] + bv[nf][0], 0.f);
                    s1 += fmaxf(acc[mf][nf][1] + bv[nf][1], 0.f);
                }
                if (r1 < rend) {
                    s0 += fmaxf(acc[mf][nf][2] + bv[nf][0], 0.f);
                    s1 += fmaxf(acc[mf][nf][3] + bv[nf][1], 0.f);
                }
            }
#pragma unroll
            for (int off = 16; off >= 4; off >>= 1) {
                s0 += __shfl_xor_sync(0xffffffffu, s0, off);
                s1 += __shfl_xor_sync(0xffffffffu, s1, off);
            }
            if (lane < 4) {
                int c = col0 + warp_n * 32 + nf * 8 + lane * 2;
                atomicAdd(&g_psum[k * DH + c], s0);
                atomicAdd(&g_psum[k * DH + c + 1], s1);
            }
        }
    }
}

// ---------------- parallel head ----------------
__global__ __launch_bounds__(256) void k_headB(const float* __restrict__ fc_W,
                                               const float* __restrict__ fc_b,
                                               const float* __restrict__ bc) {
    int gt = blockIdx.x * 256 + threadIdx.x;
    if (gt < KC) g_Alog[gt] = bc[0];
    int wid = gt >> 5;
    int lane = threadIdx.x & 31;
    if (wid >= KC * DH) return;
    int k = wid / DH, j = wid % DH;
    int cnt = g_cnt[k];
    float inv = (cnt > 0) ? 1.f / (float)cnt : 0.f;
    const float* pr = g_psum + k * DH;
    float s = 0.f;
#pragma unroll
    for (int t = 0; t < DH / 32; t++) {
        int i = t * 32 + lane;
        s += pr[i] * __ldg(fc_W + (size_t)i * DH + j);
    }
#pragma unroll
    for (int off = 16; off > 0; off >>= 1) s += __shfl_xor_sync(0xffffffffu, s, off);
    if (lane == 0) g_hs[k * DH + j] = fmaxf(s * inv + __ldg(fc_b + j), 0.f);
}

__global__ __launch_bounds__(256) void k_headC(const float* __restrict__ Va, const float* __restrict__ ba,
                                               const float* __restrict__ Vb, const float* __restrict__ bb,
                                               const float* __restrict__ Vc) {
    int wid = (blockIdx.x * 256 + threadIdx.x) >> 5;
    int lane = threadIdx.x & 31;
    if (wid >= KC * DA) return;
    int k = wid / DA, m = wid % DA;
    const float* hr = g_hs + k * DH;
    float sa = 0.f, sb = 0.f;
#pragma unroll
    for (int t = 0; t < DH / 32; t++) {
        int j = t * 32 + lane;
        float hv = hr[j];
        sa += hv * __ldg(Va + (size_t)j * DA + m);
        sb += hv * __ldg(Vb + (size_t)j * DA + m);
    }
#pragma unroll
    for (int off = 16; off > 0; off >>= 1) {
        sa += __shfl_xor_sync(0xffffffffu, sa, off);
        sb += __shfl_xor_sync(0xffffffffu, sb, off);
    }
    if (lane == 0) {
        float contrib = tanhf(sa + __ldg(ba + m)) * (1.f / (1.f + expf(-(sb + __ldg(bb + m))))) * __ldg(Vc + m);
        atomicAdd(&g_Alog[k], contrib);
    }
}

__global__ __launch_bounds__(512) void k_tail(const float* __restrict__ rho_W, const float* __restrict__ rho_b,
                                              const float* __restrict__ cls_W, const float* __restrict__ cls_b,
                                              float* __restrict__ out, int out_size) {
    __shared__ float attw[KC];
    __shared__ float hpath[DH];
    __shared__ float part[2][DA];
    __shared__ float hp2[DA];
    __shared__ float logits_s[NCLS];
    int tid = threadIdx.x;

    if (tid == 0) {
        float mx = -1e30f;
        float al[KC];
        for (int k = 0; k < KC; k++) { al[k] = g_Alog[k]; mx = fmaxf(mx, al[k]); }
        float s = 0.f;
        for (int k = 0; k < KC; k++) { float e = expf(al[k] - mx); attw[k] = e; s += e; }
        float inv = 1.f / s;
        for (int k = 0; k < KC; k++) attw[k] *= inv;
    }
    __syncthreads();

    {
        float s = 0.f;
#pragma unroll
        for (int k = 0; k < KC; k++) s += attw[k] * g_hs[k * DH + tid];
        hpath[tid] = s;
    }
    __syncthreads();

    {
        int m = tid & 255, half = tid >> 8;
        float s = 0.f;
#pragma unroll 8
        for (int j = half * 256; j < half * 256 + 256; j++)
            s += hpath[j] * __ldg(rho_W + (size_t)j * DA + m);
        part[half][m] = s;
    }
    __syncthreads();
    if (tid < DA) hp2[tid] = fmaxf(part[0][tid] + part[1][tid] + __ldg(rho_b + tid), 0.f);
    __syncthreads();

    if (tid < 128) {
        int c = tid >> 5, lane = tid & 31;
        float s = 0.f;
#pragma unroll
        for (int t = 0; t < DA / 32; t++) {
            int m = t * 32 + lane;
            s += hp2[m] * __ldg(cls_W + m * NCLS + c);
        }
#pragma unroll
        for (int off = 16; off > 0; off >>= 1) s += __shfl_xor_sync(0xffffffffu, s, off);
        if (lane == 0) logits_s[c] = s + __ldg(cls_b + c);
    }
    __syncthreads();

    if (tid == 0) {
        float haz[NCLS], S[NCLS];
        float run = 1.f;
        int best = 0;
        float bval = logits_s[0];
        for (int c = 0; c < NCLS; c++) {
            if (logits_s[c] > bval) { bval = logits_s[c]; best = c; }
            haz[c] = 1.f / (1.f + expf(-logits_s[c]));
            run *= (1.f - haz[c]);
            S[c] = run;
        }
        float vals[9];
        for (int c = 0; c < NCLS; c++) vals[c] = haz[c];
        for (int c = 0; c < NCLS; c++) vals[NCLS + c] = S[c];
        vals[8] = (float)best;
        for (int i = 0; i < out_size && i < 9; i++) out[i] = vals[i];
    }
    for (int i = 9 + tid; i < out_size; i += 512) out[i] = 0.f;
}

// ---------------- launch ----------------
extern "C" void kernel_launch(void* const* d_in, const int* in_sizes, int n_in,
                              void* d_out, int out_size) {
    const float* x     = (const float*)d_in[0];
    const int*   cid   = (const int*)d_in[1];
    const float* W1    = (const float*)d_in[2];
    const float* b1    = (const float*)d_in[3];
    const float* W2    = (const float*)d_in[4];
    const float* b2    = (const float*)d_in[5];
    const float* fc_W  = (const float*)d_in[6];
    const float* fc_b  = (const float*)d_in[7];
    const float* Va    = (const float*)d_in[8];
    const float* ba    = (const float*)d_in[9];
    const float* Vb    = (const float*)d_in[10];
    const float* bb    = (const float*)d_in[11];
    const float* Vc    = (const float*)d_in[12];
    const float* bc    = (const float*)d_in[13];
    const float* rho_W = (const float*)d_in[14];
    const float* rho_b = (const float*)d_in[15];
    const float* cls_W = (const float*)d_in[16];
    const float* cls_b = (const float*)d_in[17];
    float* out = (float*)d_out;

    int n = in_sizes[0] / DIN;   // 8192

    k_prep<<<1, 1024>>>(cid, n);                                      // 1
    {
        dim3 b(32, 8);
        k_conv_w_all<<<dim3(48, DH / 32, KC), b>>>(W1, W2);           // 2
    }

    dim3 grid(DH / 128, (n + 127) / 128, KC);
    k_mma<DIN, 0><<<grid, 256>>>(b1, x);                              // 3  (A = fp32 x, fused convert)
    k_mma<DH, 1><<<grid, 256>>>(b2, nullptr);                         // 4

    k_headB<<<(KC * DH * 32 + 255) / 256, 256>>>(fc_W, fc_b, bc);     // 5
    k_headC<<<(KC * DA * 32 + 255) / 256, 256>>>(Va, ba, Vb, bb, Vc); // 6
    k_tail<<<1, 512>>>(rho_W, rho_b, cls_W, cls_b, out, out_size);    // 7
}

// round 12
// speedup vs baseline: 8.9314x; 1.0037x over previous
#include <cuda_runtime.h>
#include <cuda_fp16.h>
#include <math.h>
#include <stdint.h>

#define NPATCH 8192
#define NPAD   (NPATCH + 128)
#define KC     10
#define DIN    1024
#define DH     512
#define DA     256
#define NCLS   4

// ---------------- device scratch (ONLY referenced inside device code) ----------------
__device__ int   g_cnt[KC];
__device__ int   g_off[KC + 1];
__device__ int   g_order[NPATCH];
__device__ __align__(128) __half g_w1t[(size_t)KC * DH * DIN];
__device__ __align__(128) __half g_w2t[(size_t)KC * DH * DH];
__device__ __align__(128) __half g_h1 [(size_t)NPAD * DH];
__device__ float g_psum[KC * DH];
__device__ float g_hs[KC * DH];
__device__ float g_Alog[KC];

// ---------------- PTX helpers ----------------
__device__ __forceinline__ uint32_t smem_u32(const void* p) {
    uint32_t a;
    asm("{ .reg .u64 t; cvta.to.shared.u64 t, %1; cvt.u32.u64 %0, t; }" : "=r"(a) : "l"(p));
    return a;
}
#define CPASYNC16(dst, src) asm volatile("cp.async.ca.shared.global [%0], [%1], 16;" :: "r"(dst), "l"(src) : "memory")
#define CP_COMMIT()         asm volatile("cp.async.commit_group;" ::: "memory")
#define CP_WAIT(n)          asm volatile("cp.async.wait_group %0;" :: "n"(n) : "memory")

__device__ __forceinline__ void ldsm4(uint32_t& r0, uint32_t& r1, uint32_t& r2, uint32_t& r3,
                                      uint32_t addr) {
    asm volatile("ldmatrix.sync.aligned.m8n8.x4.shared.b16 {%0,%1,%2,%3}, [%4];"
                 : "=r"(r0), "=r"(r1), "=r"(r2), "=r"(r3) : "r"(addr));
}
__device__ __forceinline__ void mma_f16(float* c, uint32_t a0, uint32_t a1, uint32_t a2,
                                        uint32_t a3, uint32_t b0, uint32_t b1) {
    asm volatile("mma.sync.aligned.m16n8k16.row.col.f32.f16.f16.f32 "
                 "{%0,%1,%2,%3}, {%4,%5,%6,%7}, {%8,%9}, {%0,%1,%2,%3};"
                 : "+f"(c[0]), "+f"(c[1]), "+f"(c[2]), "+f"(c[3])
                 : "r"(a0), "r"(a1), "r"(a2), "r"(a3), "r"(b0), "r"(b1));
}
__device__ __forceinline__ uint32_t packh2(float a, float b) {
    __half2 h = __floats2half2_rn(a, b);
    return *(uint32_t*)&h;
}

// ---------------- fused prep: hist + offsets + scatter + zero psum (single block) ----------
__global__ __launch_bounds__(1024) void k_prep(const int* __restrict__ cid, int n) {
    __shared__ int scnt[KC];
    __shared__ int scur[KC];
    int tid = threadIdx.x;
    if (tid < KC) scnt[tid] = 0;
    __syncthreads();
    for (int i = tid; i < n; i += 1024) atomicAdd(&scnt[cid[i]], 1);
    __syncthreads();
    if (tid == 0) {
        int s = 0;
        g_off[0] = 0;
        for (int k = 0; k < KC; k++) {
            g_cnt[k] = scnt[k];
            scur[k] = s;
            s += scnt[k];
            g_off[k + 1] = s;
        }
    }
    __syncthreads();
    for (int i = tid; i < n; i += 1024) {
        int c = cid[i];
        int pos = atomicAdd(&scur[c], 1);
        g_order[pos] = i;
    }
    for (int i = tid; i < KC * DH; i += 1024) g_psum[i] = 0.f;
}

// fused transpose+convert of BOTH weight tensors in one launch
// blockIdx.x in [0,32): W1 k-tile; [32,48): W2 k-tile. blockIdx.y: n-tile (16). z: cluster.
__global__ void k_conv_w_all(const float* __restrict__ W1, const float* __restrict__ W2) {
    int bx = blockIdx.x;
    int isW1 = bx < 32;
    const int KD = isW1 ? DIN : DH;
    const float* W = isW1 ? W1 : W2;
    __half* out = isW1 ? g_w1t : g_w2t;
    int kk0 = (isW1 ? bx : bx - 32) * 32;

    __shared__ float t[32][33];
    int tx = threadIdx.x, ty = threadIdx.y;
    int n0 = blockIdx.y * 32, k = blockIdx.z;
    const float* src = W + (size_t)k * KD * DH;
#pragma unroll
    for (int i = 0; i < 4; i++) {
        int row = ty + i * 8;
        t[row][tx] = src[(size_t)(kk0 + row) * DH + n0 + tx];
    }
    __syncthreads();
    __half* dst = out + (size_t)k * DH * KD;
#pragma unroll
    for (int i = 0; i < 4; i++) {
        int row = ty + i * 8;
        dst[(size_t)(n0 + row) * KD + kk0 + tx] = __float2half_rn(t[tx][row]);
    }
}

// ---------------- HMMA grouped GEMM ----------------
// EPI = 0: A = fp32 x gathered+converted in-loader; out g_h1 = fp16(relu(acc+bias))
// EPI = 1: A = g_h1 (fp16, cp.async);           out psum += colsum(relu(acc+bias))
#define LDA 40

template <int KDIM, int EPI>
__global__ __launch_bounds__(256, 2) void k_mma(const float* __restrict__ bias,
                                                const float* __restrict__ xsrc) {
    const __half* Bsrc = (EPI == 0) ? g_w1t : g_w2t;

    int k = blockIdx.z;
    int rend = g_off[k + 1];
    int row0 = g_off[k] + blockIdx.y * 128;
    if (row0 >= rend) return;
    int col0 = blockIdx.x * 128;

    __shared__ __align__(16) __half sA[2][128 * LDA];
    __shared__ __align__(16) __half sB[2][128 * LDA];

    int tid = threadIdx.x;
    int wid = tid >> 5, lane = tid & 31;
    int warp_m = wid & 1;
    int warp_n = wid >> 1;

    float acc[4][4][4];
#pragma unroll
    for (int mf = 0; mf < 4; mf++)
#pragma unroll
        for (int nf = 0; nf < 4; nf++)
#pragma unroll
            for (int q = 0; q < 4; q++) acc[mf][nf][q] = 0.f;

    int lrow = tid >> 1, lhalf = tid & 1;
    uint32_t aSm[2] = {smem_u32(&sA[0][0]), smem_u32(&sA[1][0])};
    uint32_t bSm[2] = {smem_u32(&sB[0][0]), smem_u32(&sB[1][0])};

    // B loader (cp.async), same for both
    uint32_t ldOff[2];
    const __half* bSrcQ[2];
#pragma unroll
    for (int q = 0; q < 2; q++) {
        int seg = lhalf * 2 + q;
        ldOff[q] = (uint32_t)(lrow * LDA + seg * 8) * 2;
        bSrcQ[q] = Bsrc + ((size_t)k * DH + col0 + lrow) * KDIM + seg * 8;
    }

    // A loader sources
    int arow = row0 + lrow;
    int arow_cl = (arow < rend) ? arow : (rend - 1);
    const float4* xq = nullptr;       // EPI==0: fp32 gathered
    const __half* aSrcQ[2] = {nullptr, nullptr};  // EPI==1: fp16 direct
    if (EPI == 0) {
        xq = (const float4*)(xsrc + (size_t)g_order[arow_cl] * DIN + lhalf * 16);
    } else {
#pragma unroll
        for (int q = 0; q < 2; q++) {
            int seg = lhalf * 2 + q;
            aSrcQ[q] = g_h1 + (size_t)arow * KDIM + seg * 8;
        }
    }
    __half* aSts = &sA[0][0] + (lrow * LDA + lhalf * 16);   // buf0 base; buf1 = +128*LDA

    int lane15 = lane & 15, lanehi = lane >> 4;
    uint32_t offA[4], offB[2];
#pragma unroll
    for (int mf = 0; mf < 4; mf++)
        offA[mf] = (uint32_t)((warp_m * 64 + mf * 16 + lane15) * LDA + lanehi * 8) * 2;
#pragma unroll
    for (int ng = 0; ng < 2; ng++)
        offB[ng] = (uint32_t)((warp_n * 32 + ng * 16 + lane15) * LDA + lanehi * 8) * 2;

    const int NCH = KDIM / 32;

    auto compute = [&](int buf) {
#pragma unroll
        for (int ks = 0; ks < 2; ks++) {
            uint32_t kof = ks * 32;
            uint32_t afr[4][4], bfr[4][2];
#pragma unroll
            for (int mf = 0; mf < 4; mf++)
                ldsm4(afr[mf][0], afr[mf][1], afr[mf][2], afr[mf][3], aSm[buf] + offA[mf] + kof);
#pragma unroll
            for (int ng = 0; ng < 2; ng++) {
                uint32_t r0, r1, r2, r3;
                ldsm4(r0, r1, r2, r3, bSm[buf] + offB[ng] + kof);
                bfr[ng * 2 + 0][0] = r0; bfr[ng * 2 + 0][1] = r2;
                bfr[ng * 2 + 1][0] = r1; bfr[ng * 2 + 1][1] = r3;
            }
#pragma unroll
            for (int mf = 0; mf < 4; mf++)
#pragma unroll
                for (int nf = 0; nf < 4; nf++)
                    mma_f16(acc[mf][nf], afr[mf][0], afr[mf][1], afr[mf][2], afr[mf][3],
                            bfr[nf][0], bfr[nf][1]);
        }
    };

    if (EPI == 0) {
        // ---- A: fp32 LDG + convert + STS (register prefetch); B: cp.async ----
        float4 fa[4];
#pragma unroll
        for (int q = 0; q < 4; q++) fa[q] = __ldg(xq + q);
#pragma unroll
        for (int q = 0; q < 2; q++) CPASYNC16(bSm[0] + ldOff[q], bSrcQ[q]);
        CP_COMMIT();

        for (int s = 0; s < NCH; s++) {
            int buf = s & 1;
            {   // convert + store current A chunk
                uint32_t hw[8];
#pragma unroll
                for (int q = 0; q < 4; q++) {
                    hw[2 * q + 0] = packh2(fa[q].x, fa[q].y);
                    hw[2 * q + 1] = packh2(fa[q].z, fa[q].w);
                }
                uint4* d = (uint4*)(aSts + buf * 128 * LDA);
                d[0] = make_uint4(hw[0], hw[1], hw[2], hw[3]);
                d[1] = make_uint4(hw[4], hw[5], hw[6], hw[7]);
            }
            if (s + 1 < NCH) {
                int nb = (s + 1) & 1;
#pragma unroll
                for (int q = 0; q < 2; q++)
                    CPASYNC16(bSm[nb] + ldOff[q], bSrcQ[q] + (size_t)(s + 1) * 32);
                CP_COMMIT();
                CP_WAIT(1);
            } else {
                CP_WAIT(0);
            }
            __syncthreads();
            if (s + 1 < NCH) {
#pragma unroll
                for (int q = 0; q < 4; q++) fa[q] = __ldg(xq + (s + 1) * 8 + q);
            }
            compute(buf);
            __syncthreads();
        }
    } else {
        // ---- both A and B via cp.async (A rows already cluster-sorted in g_h1) ----
#pragma unroll
        for (int q = 0; q < 2; q++) {
            CPASYNC16(aSm[0] + ldOff[q], aSrcQ[q]);
            CPASYNC16(bSm[0] + ldOff[q], bSrcQ[q]);
        }
        CP_COMMIT();

        for (int s = 0; s < NCH; s++) {
            int buf = s & 1;
            if (s + 1 < NCH) {
                int nb = (s + 1) & 1;
#pragma unroll
                for (int q = 0; q < 2; q++) {
                    CPASYNC16(aSm[nb] + ldOff[q], aSrcQ[q] + (size_t)(s + 1) * 32);
                    CPASYNC16(bSm[nb] + ldOff[q], bSrcQ[q] + (size_t)(s + 1) * 32);
                }
                CP_COMMIT();
                CP_WAIT(1);
            } else {
                CP_WAIT(0);
            }
            __syncthreads();
            compute(buf);
            __syncthreads();
        }
    }

    // ---------------- epilogue ----------------
    const float* bp = bias + k * DH + col0 + warp_n * 32;
    float bv[4][2];
#pragma unroll
    for (int nf = 0; nf < 4; nf++) {
        bv[nf][0] = __ldg(bp + nf * 8 + (lane & 3) * 2);
        bv[nf][1] = __ldg(bp + nf * 8 + (lane & 3) * 2 + 1);
    }
    int rbase = row0 + warp_m * 64 + (lane >> 2);

    if (EPI == 0) {
#pragma unroll
        for (int mf = 0; mf < 4; mf++) {
#pragma unroll
            for (int half = 0; half < 2; half++) {
                int r = rbase + mf * 16 + half * 8;
                if (r >= rend) continue;
#pragma unroll
                for (int nf = 0; nf < 4; nf++) {
                    int c = col0 + warp_n * 32 + nf * 8 + (lane & 3) * 2;
                    float v0 = fmaxf(acc[mf][nf][half * 2 + 0] + bv[nf][0], 0.f);
                    float v1 = fmaxf(acc[mf][nf][half * 2 + 1] + bv[nf][1], 0.f);
                    *(__half2*)(g_h1 + (size_t)r * DH + c) = __floats2half2_rn(v0, v1);
                }
            }
        }
    } else {
#pragma unroll
        for (int nf = 0; nf < 4; nf++) {
            float s0 = 0.f, s1 = 0.f;
#pragma unroll
            for (int mf = 0; mf < 4; mf++) {
                int r0 = rbase + mf * 16;
                int r1 = r0 + 8;
                if (r0 < rend) {
                    s0 += fmaxf(acc[mf][nf][0] + bv[nf][0], 0.f);
                    s1 += fmaxf(acc[mf][nf][1] + bv[nf][1], 0.f);
                }
                if (r1 < rend) {
                    s0 += fmaxf(acc[mf][nf][2] + bv[nf][0], 0.f);
                    s1 += fmaxf(acc[mf][nf][3] + bv[nf][1], 0.f);
                }
            }
#pragma unroll
            for (int off = 16; off >= 4; off >>= 1) {
                s0 += __shfl_xor_sync(0xffffffffu, s0, off);
                s1 += __shfl_xor_sync(0xffffffffu, s1, off);
            }
            if (lane < 4) {
                int c = col0 + warp_n * 32 + nf * 8 + lane * 2;
                atomicAdd(&g_psum[k * DH + c], s0);
                atomicAdd(&g_psum[k * DH + c + 1], s1);
            }
        }
    }
}

// ---------------- parallel head ----------------
__global__ __launch_bounds__(256) void k_headB(const float* __restrict__ fc_W,
                                               const float* __restrict__ fc_b,
                                               const float* __restrict__ bc) {
    int gt = blockIdx.x * 256 + threadIdx.x;
    if (gt < KC) g_Alog[gt] = bc[0];
    int wid = gt >> 5;
    int lane = threadIdx.x & 31;
    if (wid >= KC * DH) return;
    int k = wid / DH, j = wid % DH;
    int cnt = g_cnt[k];
    float inv = (cnt > 0) ? 1.f / (float)cnt : 0.f;
    const float* pr = g_psum + k * DH;
    float s = 0.f;
#pragma unroll
    for (int t = 0; t < DH / 32; t++) {
        int i = t * 32 + lane;
        s += pr[i] * __ldg(fc_W + (size_t)i * DH + j);
    }
#pragma unroll
    for (int off = 16; off > 0; off >>= 1) s += __shfl_xor_sync(0xffffffffu, s, off);
    if (lane == 0) g_hs[k * DH + j] = fmaxf(s * inv + __ldg(fc_b + j), 0.f);
}

__global__ __launch_bounds__(256) void k_headC(const float* __restrict__ Va, const float* __restrict__ ba,
                                               const float* __restrict__ Vb, const float* __restrict__ bb,
                                               const float* __restrict__ Vc) {
    int wid = (blockIdx.x * 256 + threadIdx.x) >> 5;
    int lane = threadIdx.x & 31;
    if (wid >= KC * DA) return;
    int k = wid / DA, m = wid % DA;
    const float* hr = g_hs + k * DH;
    float sa = 0.f, sb = 0.f;
#pragma unroll
    for (int t = 0; t < DH / 32; t++) {
        int j = t * 32 + lane;
        float hv = hr[j];
        sa += hv * __ldg(Va + (size_t)j * DA + m);
        sb += hv * __ldg(Vb + (size_t)j * DA + m);
    }
#pragma unroll
    for (int off = 16; off > 0; off >>= 1) {
        sa += __shfl_xor_sync(0xffffffffu, sa, off);
        sb += __shfl_xor_sync(0xffffffffu, sb, off);
    }
    if (lane == 0) {
        float contrib = tanhf(sa + __ldg(ba + m)) * (1.f / (1.f + expf(-(sb + __ldg(bb + m))))) * __ldg(Vc + m);
        atomicAdd(&g_Alog[k], contrib);
    }
}

__global__ __launch_bounds__(512) void k_tail(const float* __restrict__ rho_W, const float* __restrict__ rho_b,
                                              const float* __restrict__ cls_W, const float* __restrict__ cls_b,
                                              float* __restrict__ out, int out_size) {
    __shared__ float attw[KC];
    __shared__ float hpath[DH];
    __shared__ float part[2][DA];
    __shared__ float hp2[DA];
    __shared__ float logits_s[NCLS];
    int tid = threadIdx.x;

    if (tid == 0) {
        float mx = -1e30f;
        float al[KC];
        for (int k = 0; k < KC; k++) { al[k] = g_Alog[k]; mx = fmaxf(mx, al[k]); }
        float s = 0.f;
        for (int k = 0; k < KC; k++) { float e = expf(al[k] - mx); attw[k] = e; s += e; }
        float inv = 1.f / s;
        for (int k = 0; k < KC; k++) attw[k] *= inv;
    }
    __syncthreads();

    {
        float s = 0.f;
#pragma unroll
        for (int k = 0; k < KC; k++) s += attw[k] * g_hs[k * DH + tid];
        hpath[tid] = s;
    }
    __syncthreads();

    {
        int m = tid & 255, half = tid >> 8;
        float s = 0.f;
#pragma unroll 8
        for (int j = half * 256; j < half * 256 + 256; j++)
            s += hpath[j] * __ldg(rho_W + (size_t)j * DA + m);
        part[half][m] = s;
    }
    __syncthreads();
    if (tid < DA) hp2[tid] = fmaxf(part[0][tid] + part[1][tid] + __ldg(rho_b + tid), 0.f);
    __syncthreads();

    if (tid < 128) {
        int c = tid >> 5, lane = tid & 31;
        float s = 0.f;
#pragma unroll
        for (int t = 0; t < DA / 32; t++) {
            int m = t * 32 + lane;
            s += hp2[m] * __ldg(cls_W + m * NCLS + c);
        }
#pragma unroll
        for (int off = 16; off > 0; off >>= 1) s += __shfl_xor_sync(0xffffffffu, s, off);
        if (lane == 0) logits_s[c] = s + __ldg(cls_b + c);
    }
    __syncthreads();

    if (tid == 0) {
        float haz[NCLS], S[NCLS];
        float run = 1.f;
        int best = 0;
        float bval = logits_s[0];
        for (int c = 0; c < NCLS; c++) {
            if (logits_s[c] > bval) { bval = logits_s[c]; best = c; }
            haz[c] = 1.f / (1.f + expf(-logits_s[c]));
            run *= (1.f - haz[c]);
            S[c] = run;
        }
        float vals[9];
        for (int c = 0; c < NCLS; c++) vals[c] = haz[c];
        for (int c = 0; c < NCLS; c++) vals[NCLS + c] = S[c];
        vals[8] = (float)best;
        for (int i = 0; i < out_size && i < 9; i++) out[i] = vals[i];
    }
    for (int i = 9 + tid; i < out_size; i += 512) out[i] = 0.f;
}

// ---------------- launch ----------------
extern "C" void kernel_launch(void* const* d_in, const int* in_sizes, int n_in,
                              void* d_out, int out_size) {
    const float* x     = (const float*)d_in[0];
    const int*   cid   = (const int*)d_in[1];
    const float* W1    = (const float*)d_in[2];
    const float* b1    = (const float*)d_in[3];
    const float* W2    = (const float*)d_in[4];
    const float* b2    = (const float*)d_in[5];
    const float* fc_W  = (const float*)d_in[6];
    const float* fc_b  = (const float*)d_in[7];
    const float* Va    = (const float*)d_in[8];
    const float* ba    = (const float*)d_in[9];
    const float* Vb    = (const float*)d_in[10];
    const float* bb    = (const float*)d_in[11];
    const float* Vc    = (const float*)d_in[12];
    const float* bc    = (const float*)d_in[13];
    const float* rho_W = (const float*)d_in[14];
    const float* rho_b = (const float*)d_in[15];
    const float* cls_W = (const float*)d_in[16];
    const float* cls_b = (const float*)d_in[17];
    float* out = (float*)d_out;

    int n = in_sizes[0] / DIN;   // 8192

    k_prep<<<1, 1024>>>(cid, n);                                      // 1
    {
        dim3 b(32, 8);
        k_conv_w_all<<<dim3(48, DH / 32, KC), b>>>(W1, W2);           // 2
    }

    dim3 grid(DH / 128, (n + 127) / 128, KC);
    k_mma<DIN, 0><<<grid, 256>>>(b1, x);                              // 3  (A = fp32 x, fused convert)
    k_mma<DH, 1><<<grid, 256>>>(b2, nullptr);                         // 4

    k_headB<<<(KC * DH * 32 + 255) / 256, 256>>>(fc_W, fc_b, bc);     // 5
    k_headC<<<(KC * DA * 32 + 255) / 256, 256>>>(Va, ba, Vb, bb, Vc); // 6
    k_tail<<<1, 512>>>(rho_W, rho_b, cls_W, cls_b, out, out_size);    // 7
}